// round 4
// baseline (speedup 1.0000x reference)
#include <cuda_runtime.h>
#include <math.h>

#define NP   128
#define DD   2048
#define NN   16384
#define NBLK 128
#define NTHR 256
#define ZSL  32      // K slices in phase A

// ---------------- scratch (no allocations allowed) ----------------
__device__ float    g_part[ZSL*NN];   // phase-A partials of Q = V G^T   (2 MB)
__device__ float    g_P[NN];          // P = V G^T / n
__device__ float    g_S2[2*NN];       // S = n P P^T in two K-halves (sum them)
__device__ float    g_consts[2];      // inv2h, invh
__device__ unsigned g_sense;
__device__ unsigned g_count;

// ---------------- shared memory union ----------------
struct SmemAll {
    union {
        struct { float4 As4[64][17]; float4 Bs4[64][17]; } a;           // 34.8 KB GEMM
        struct { float sdiag[128]; unsigned hist[256]; unsigned wsum[8];
                 unsigned sel[4]; unsigned cnt; unsigned list[512]; } m; // median
        struct { float sd[128]; float rs[8];
                 float4 Wk4[8][32]; float pacc[2][8][128];
                 float4 Wb4[8][32]; } e;                                 // ~17 KB EF
    };
};

// ---------------- acquire/release helpers ----------------
__device__ __forceinline__ unsigned ld_acq(unsigned* p) {
    unsigned v;
    asm volatile("ld.acquire.gpu.u32 %0, [%1];" : "=r"(v) : "l"(p) : "memory");
    return v;
}
__device__ __forceinline__ void st_rel(unsigned* p, unsigned v) {
    asm volatile("st.release.gpu.u32 [%0], %1;" :: "l"(p), "r"(v) : "memory");
}

// ---------------- grid-wide barrier ----------------
__device__ __forceinline__ void gbar(unsigned& lsense) {
    unsigned target = lsense ^ 1u;
    __syncthreads();
    if (threadIdx.x == 0) {
        __threadfence();
        if (atomicAdd(&g_count, 1u) == NBLK - 1u) {
            g_count = 0u;
            st_rel(&g_sense, target);
        } else {
            while (ld_acq(&g_sense) != target) { }
        }
    }
    __syncthreads();
    lsense = target;
}

// ============================================================
// 64x64 output tile of A(row-major,[*,K]) x B(row-major,[*,K])^T over a
// 64-wide K chunk. K-major smem with XOR swizzle; conflict-free loads.
// Thread (tx,ty) in 16x16 computes rows 4ty..+3, cols 4tx..+3.
// ============================================================
__device__ __forceinline__ void dot64(SmemAll* sm,
                                      const float* __restrict__ A,
                                      const float* __restrict__ B,
                                      float* __restrict__ C,
                                      int arow0, int brow0, int k0, int K,
                                      float scale)
{
    int t = threadIdx.x, tx = t & 15, ty = t >> 4;
    const float4* A4 = (const float4*)A;
    const float4* B4 = (const float4*)B;
    int K4 = K >> 2, q0 = k0 >> 2;
    float* Asf = (float*)&sm->a.As4[0][0];   // row stride 68 floats
    float* Bsf = (float*)&sm->a.Bs4[0][0];

    #pragma unroll
    for (int p = 0; p < 4; p++) {
        int idx = t + p * 256;
        int r = idx >> 4, q = idx & 15;          // r: row 0..63, q: k-group 0..15
        float4 va = A4[(arow0 + r) * K4 + q0 + q];
        float4 vb = B4[(brow0 + r) * K4 + q0 + q];
        int cp = (((r >> 2) ^ q) << 2) | (r & 3);  // swizzled column position
        int kb = 4 * q;
        Asf[(kb    ) * 68 + cp] = va.x;
        Asf[(kb + 1) * 68 + cp] = va.y;
        Asf[(kb + 2) * 68 + cp] = va.z;
        Asf[(kb + 3) * 68 + cp] = va.w;
        Bsf[(kb    ) * 68 + cp] = vb.x;
        Bsf[(kb + 1) * 68 + cp] = vb.y;
        Bsf[(kb + 2) * 68 + cp] = vb.z;
        Bsf[(kb + 3) * 68 + cp] = vb.w;
    }
    __syncthreads();

    float acc[4][4];
    #pragma unroll
    for (int i = 0; i < 4; i++)
        #pragma unroll
        for (int j = 0; j < 4; j++) acc[i][j] = 0.f;

    #pragma unroll 8
    for (int k = 0; k < 64; k++) {
        int s = k >> 2;
        float4 av = sm->a.As4[k][ty ^ s];
        float4 bv = sm->a.Bs4[k][tx ^ s];
        acc[0][0] += av.x*bv.x; acc[0][1] += av.x*bv.y; acc[0][2] += av.x*bv.z; acc[0][3] += av.x*bv.w;
        acc[1][0] += av.y*bv.x; acc[1][1] += av.y*bv.y; acc[1][2] += av.y*bv.z; acc[1][3] += av.y*bv.w;
        acc[2][0] += av.z*bv.x; acc[2][1] += av.z*bv.y; acc[2][2] += av.z*bv.z; acc[2][3] += av.z*bv.w;
        acc[3][0] += av.w*bv.x; acc[3][1] += av.w*bv.y; acc[3][2] += av.w*bv.z; acc[3][3] += av.w*bv.w;
    }
    #pragma unroll
    for (int i = 0; i < 4; i++) {
        float4 o = make_float4(acc[i][0]*scale, acc[i][1]*scale, acc[i][2]*scale, acc[i][3]*scale);
        *(float4*)&C[(arow0 + 4*ty + i) * NP + brow0 + 4*tx] = o;
    }
}

__device__ __forceinline__ unsigned f2key(float d) {
    unsigned u = __float_as_uint(d);
    return (u & 0x80000000u) ? ~u : (u | 0x80000000u);
}

// ==================================================================
__global__ void __launch_bounds__(NTHR, 1)
stein_fused(const float* __restrict__ V, const float* __restrict__ G,
            float* __restrict__ out)
{
    __shared__ SmemAll sm;
    int b = blockIdx.x, t = threadIdx.x;
    unsigned lsense = g_sense;   // snapshot (replay-safe)

    // ---- Phase A: Q partials, 4 tiles x 32 K-slices of 64 ----
    {
        int tile = b & 3, z = b >> 2;
        dot64(&sm, V, G, g_part + z * NN, (tile >> 1) * 64, (tile & 1) * 64,
              z * 64, DD, 1.0f);
    }
    gbar(lsense);

    // ---- Phase B: reduce 32 partials -> P (blocks 0..63) ----
    if (b < 64) {
        int e0 = b * 256 + t;
        float s = 0.f;
        #pragma unroll
        for (int z = 0; z < ZSL; z++) s += g_part[z * NN + e0];
        g_P[e0] = s * (1.0f / 128.0f);
    }
    gbar(lsense);

    // ---- Phase C: S halves = 128 * P P^T (blocks 64..71) ----
    if (b >= 64 && b < 72) {
        int id = b - 64;
        int kh = id & 1, tile = id >> 1;
        dot64(&sm, g_P, g_P, g_S2 + kh * NN, (tile >> 1) * 64, (tile & 1) * 64,
              kh * 64, NP, 128.0f);
    }
    gbar(lsense);

    // ---- Phase M: median of dMsd (block 0 only) ----
    if (b == 0) {
        int lane = t & 31, wid = t >> 5;
        if (t < 128) sm.m.sdiag[t] = g_S2[t * NP + t] + g_S2[NN + t * NP + t];
        __syncthreads();

        unsigned keys[64];
        {
            int i = t >> 1, j0 = (t & 1) * 64;
            float sdi = sm.m.sdiag[i];
            #pragma unroll 8
            for (int e = 0; e < 64; e++) {
                int j = j0 + e;
                float d = sdi + sm.m.sdiag[j]
                        - (g_S2[i*NP + j] + g_S2[NN + i*NP + j])
                        - (g_S2[j*NP + i] + g_S2[NN + j*NP + i]);
                keys[e] = f2key(d);
            }
        }

        unsigned hi_mask = 0u, hi_val = 0u, krank = 8192u;
        int mode = 0;   // 0 = continue, 1 = list-select, 2 = exact
        for (int p = 0; p < 4 && mode == 0; p++) {
            int shift = 24 - 8 * p;
            sm.m.hist[t] = 0u;
            __syncthreads();
            #pragma unroll
            for (int e = 0; e < 64; e++) {
                unsigned key = keys[e];
                bool ok = (key & hi_mask) == hi_val;
                unsigned bin = ok ? ((key >> shift) & 255u) : 0xFFFFFFFFu;
                unsigned mm = __match_any_sync(0xFFFFFFFFu, bin);
                if (ok && ((int)(__ffs(mm) - 1) == lane))
                    atomicAdd(&sm.m.hist[bin], (unsigned)__popc(mm));
            }
            __syncthreads();
            // parallel scan of 256 bins
            unsigned v = sm.m.hist[t], incl = v;
            #pragma unroll
            for (int off = 1; off < 32; off <<= 1) {
                unsigned nv = __shfl_up_sync(0xFFFFFFFFu, incl, off);
                if (lane >= off) incl += nv;
            }
            if (lane == 31) sm.m.wsum[wid] = incl;
            __syncthreads();
            if (t < 8) {
                unsigned w = sm.m.wsum[t], in2 = w;
                #pragma unroll
                for (int off = 1; off < 8; off <<= 1) {
                    unsigned nv = __shfl_up_sync(0xFFu, in2, off);
                    if (t >= off) in2 += nv;
                }
                sm.m.wsum[t] = in2 - w;
            }
            __syncthreads();
            unsigned excl = incl - v + sm.m.wsum[wid];
            if (excl <= krank && krank < excl + v) {
                sm.m.sel[0] = (unsigned)t;
                sm.m.sel[1] = krank - excl;
                sm.m.sel[2] = v;
            }
            __syncthreads();
            hi_mask |= (0xFFu << shift);
            hi_val  |= (sm.m.sel[0] << shift);
            krank    = sm.m.sel[1];
            unsigned bc = sm.m.sel[2];
            if (shift == 0)       mode = 2;
            else if (bc <= 512u)  mode = 1;
            if (t == 0) sm.m.cnt = 0u;
            __syncthreads();
        }

        unsigned medkey = hi_val;
        if (mode == 1) {
            #pragma unroll
            for (int e = 0; e < 64; e++) {
                unsigned key = keys[e];
                if ((key & hi_mask) == hi_val) {
                    unsigned pos = atomicAdd(&sm.m.cnt, 1u);
                    if (pos < 512u) sm.m.list[pos] = key;
                }
            }
            __syncthreads();
            int L = (int)sm.m.cnt; if (L > 512) L = 512;
            for (int x = t; x < L; x += NTHR) {
                unsigned key = sm.m.list[x];
                unsigned less = 0, eq = 0;
                for (int j = 0; j < L; j++) {
                    unsigned kv = sm.m.list[j];
                    less += (kv < key);
                    eq   += (kv == key);
                }
                if (less <= krank && krank < less + eq) sm.m.sel[3] = key;
            }
            __syncthreads();
            medkey = sm.m.sel[3];
        }
        if (t == 0) {
            unsigned u = (medkey & 0x80000000u) ? (medkey ^ 0x80000000u) : ~medkey;
            float med = __uint_as_float(u);
            float h = (med * med) / 6.9314718f;   // ln(128)
            g_consts[0] = 0.5f / h;
            g_consts[1] = 1.0f / h;
        }
    }
    gbar(lsense);

    // ---- Phase EF: W rows (8 per block) + out = W @ G ----
    {
        int r0 = (b >> 3) * 8, cg = b & 7;
        float inv2h = g_consts[0], invh = g_consts[1];
        float* Wk = (float*)&sm.e.Wk4[0][0];
        float* Wb = (float*)&sm.e.Wb4[0][0];

        if (t < 128) sm.e.sd[t] = g_S2[t * NP + t] + g_S2[NN + t * NP + t];
        __syncthreads();

        // kern rows r0..r0+7
        #pragma unroll
        for (int p = 0; p < 4; p++) {
            int idx = t + p * 256;
            int r = idx >> 7, j = idx & 127;
            int i = r0 + r;
            float d = sm.e.sd[i] + sm.e.sd[j]
                    - (g_S2[i*NP + j] + g_S2[NN + i*NP + j])
                    - (g_S2[j*NP + i] + g_S2[NN + j*NP + i]);
            Wk[r * 128 + j] = __expf(-d * inv2h);
        }
        __syncthreads();

        // rowsums: warp w reduces row w
        {
            int w = t >> 5, l = t & 31;
            float v = Wk[w*128 + l] + Wk[w*128 + l + 32]
                    + Wk[w*128 + l + 64] + Wk[w*128 + l + 96];
            #pragma unroll
            for (int off = 16; off > 0; off >>= 1)
                v += __shfl_down_sync(0xFFFFFFFFu, v, off);
            if (l == 0) sm.e.rs[w] = v;
        }
        __syncthreads();

        // kern @ P  (split j across two halves)
        {
            int c = t & 127, h2 = t >> 7;
            float acc8[8];
            #pragma unroll
            for (int r = 0; r < 8; r++) acc8[r] = 0.f;
            int jb0 = h2 * 16;             // float4 groups
            #pragma unroll 4
            for (int j4 = jb0; j4 < jb0 + 16; j4++) {
                int j = 4 * j4;
                float p0 = g_P[(j    ) * NP + c];
                float p1 = g_P[(j + 1) * NP + c];
                float p2 = g_P[(j + 2) * NP + c];
                float p3 = g_P[(j + 3) * NP + c];
                #pragma unroll
                for (int r = 0; r < 8; r++) {
                    float4 w4 = sm.e.Wk4[r][j4];
                    acc8[r] += w4.x*p0 + w4.y*p1 + w4.z*p2 + w4.w*p3;
                }
            }
            #pragma unroll
            for (int r = 0; r < 8; r++) sm.e.pacc[h2][r][c] = acc8[r];
        }
        __syncthreads();

        // combine into Wb
        {
            int c = t & 127, h2 = t >> 7;
            #pragma unroll
            for (int rr = 0; rr < 4; rr++) {
                int r = h2 * 4 + rr, i = r0 + r;
                float a = sm.e.pacc[0][r][c] + sm.e.pacc[1][r][c];
                Wb[r * 128 + c] = Wk[r * 128 + c]
                                + invh * (a - sm.e.rs[r] * g_P[i * NP + c]);
            }
        }
        __syncthreads();

        // out rows r0..r0+7, cols cg*256..+255
        {
            int c2 = cg * 256 + t;
            float acc[8];
            #pragma unroll
            for (int r = 0; r < 8; r++) acc[r] = 0.f;
            #pragma unroll 2
            for (int j4 = 0; j4 < 32; j4++) {
                int j = 4 * j4;
                float g0 = G[(j    ) * DD + c2];
                float g1 = G[(j + 1) * DD + c2];
                float g2 = G[(j + 2) * DD + c2];
                float g3 = G[(j + 3) * DD + c2];
                #pragma unroll
                for (int r = 0; r < 8; r++) {
                    float4 w4 = sm.e.Wb4[r][j4];
                    acc[r] += w4.x*g0 + w4.y*g1 + w4.z*g2 + w4.w*g3;
                }
            }
            #pragma unroll
            for (int r = 0; r < 8; r++) out[(r0 + r) * DD + c2] = acc[r];
        }
    }
}

extern "C" void kernel_launch(void* const* d_in, const int* in_sizes, int n_in,
                              void* d_out, int out_size)
{
    const float* var  = (const float*)d_in[0];
    const float* grad = (const float*)d_in[1];
    float* out = (float*)d_out;
    stein_fused<<<NBLK, NTHR>>>(var, grad, out);
}

// round 5
// speedup vs baseline: 1.0262x; 1.0262x over previous
#include <cuda_runtime.h>
#include <math.h>

#define NP   128
#define DD   2048
#define NN   16384
#define NBLK 128
#define NTHR 512
#define ZSL  32      // K slices in phase A

// ---------------- scratch (no allocations allowed) ----------------
__device__ float    g_part[ZSL*NN];   // phase-A partials of Q = V G^T   (2 MB)
__device__ float    g_P[NN];          // P = V G^T / n
__device__ float    g_S2[2*NN];       // S = n P P^T in two K-halves (sum them)
__device__ float    g_consts[2];      // inv2h, invh
__device__ unsigned g_sense;
__device__ unsigned g_count;

// ---------------- shared memory union ----------------
struct SmemAll {
    union {
        struct { float4 As4[64][17]; float4 Bs4[64][17]; } a;            // 34.8 KB GEMM
        struct { float4 pc[256][4]; } r;                                  // 16 KB kh-combine
        struct { float sdiag[128]; unsigned hist[256]; unsigned wsum[8];
                 unsigned sel[4]; unsigned cnt; unsigned list[512]; } m;  // median
        struct { float sd[128]; float rs[8];
                 float4 Wk4[8][32]; float pacc[4][8][128];
                 float4 Wb4[8][32]; } e;                                  // ~25 KB EF
    };
};

// ---------------- acquire/release helpers ----------------
__device__ __forceinline__ unsigned ld_acq(unsigned* p) {
    unsigned v;
    asm volatile("ld.acquire.gpu.u32 %0, [%1];" : "=r"(v) : "l"(p) : "memory");
    return v;
}
__device__ __forceinline__ void st_rel(unsigned* p, unsigned v) {
    asm volatile("st.release.gpu.u32 [%0], %1;" :: "l"(p), "r"(v) : "memory");
}

// ---------------- grid-wide barrier ----------------
__device__ __forceinline__ void gbar(unsigned& lsense) {
    unsigned target = lsense ^ 1u;
    __syncthreads();
    if (threadIdx.x == 0) {
        __threadfence();
        if (atomicAdd(&g_count, 1u) == NBLK - 1u) {
            g_count = 0u;
            st_rel(&g_sense, target);
        } else {
            while (ld_acq(&g_sense) != target) { }
        }
    }
    __syncthreads();
    lsense = target;
}

// ============================================================
// 64x64 tile of A x B^T over a 64-wide K chunk, 512 threads.
// Threads (tx,ty,kh): kh in {0,1} splits K 32+32; smem combine at end.
// ============================================================
__device__ __forceinline__ void dot64w(SmemAll* sm,
                                       const float* __restrict__ A,
                                       const float* __restrict__ B,
                                       float* __restrict__ C,
                                       int arow0, int brow0, int k0, int K,
                                       float scale)
{
    int t = threadIdx.x;
    int tx = t & 15, ty = (t >> 4) & 15, kh = t >> 8;
    const float4* A4 = (const float4*)A;
    const float4* B4 = (const float4*)B;
    int K4 = K >> 2, q0 = k0 >> 2;
    float* Asf = (float*)&sm->a.As4[0][0];   // row stride 68 floats
    float* Bsf = (float*)&sm->a.Bs4[0][0];

    #pragma unroll
    for (int p = 0; p < 4; p++) {
        int idx = t + p * 512;                  // 0..2047
        int mat = idx >> 10;                    // 0=A, 1=B
        int r = (idx >> 4) & 63, q = idx & 15;
        const float4* S4 = mat ? B4 : A4;
        float* D = mat ? Bsf : Asf;
        int row0 = mat ? brow0 : arow0;
        float4 v = S4[(row0 + r) * K4 + q0 + q];
        int cp = (((r >> 2) ^ q) << 2) | (r & 3);
        int kb = 4 * q;
        D[(kb    ) * 68 + cp] = v.x;
        D[(kb + 1) * 68 + cp] = v.y;
        D[(kb + 2) * 68 + cp] = v.z;
        D[(kb + 3) * 68 + cp] = v.w;
    }
    __syncthreads();

    float acc[4][4];
    #pragma unroll
    for (int i = 0; i < 4; i++)
        #pragma unroll
        for (int j = 0; j < 4; j++) acc[i][j] = 0.f;

    int kb0 = kh * 32;
    #pragma unroll 8
    for (int k = kb0; k < kb0 + 32; k++) {
        int s = k >> 2;
        float4 av = sm->a.As4[k][ty ^ s];
        float4 bv = sm->a.Bs4[k][tx ^ s];
        acc[0][0] += av.x*bv.x; acc[0][1] += av.x*bv.y; acc[0][2] += av.x*bv.z; acc[0][3] += av.x*bv.w;
        acc[1][0] += av.y*bv.x; acc[1][1] += av.y*bv.y; acc[1][2] += av.y*bv.z; acc[1][3] += av.y*bv.w;
        acc[2][0] += av.z*bv.x; acc[2][1] += av.z*bv.y; acc[2][2] += av.z*bv.z; acc[2][3] += av.z*bv.w;
        acc[3][0] += av.w*bv.x; acc[3][1] += av.w*bv.y; acc[3][2] += av.w*bv.z; acc[3][3] += av.w*bv.w;
    }
    __syncthreads();                            // done reading As/Bs (aliased by pc)
    int slot = ty * 16 + tx;
    if (kh == 1) {
        #pragma unroll
        for (int i = 0; i < 4; i++)
            sm->r.pc[slot][i] = make_float4(acc[i][0], acc[i][1], acc[i][2], acc[i][3]);
    }
    __syncthreads();
    if (kh == 0) {
        #pragma unroll
        for (int i = 0; i < 4; i++) {
            float4 o = sm->r.pc[slot][i];
            o.x = (o.x + acc[i][0]) * scale;
            o.y = (o.y + acc[i][1]) * scale;
            o.z = (o.z + acc[i][2]) * scale;
            o.w = (o.w + acc[i][3]) * scale;
            *(float4*)&C[(arow0 + 4*ty + i) * NP + brow0 + 4*tx] = o;
        }
    }
}

__device__ __forceinline__ unsigned f2key(float d) {
    unsigned u = __float_as_uint(d);
    return (u & 0x80000000u) ? ~u : (u | 0x80000000u);
}

// ==================================================================
__global__ void __launch_bounds__(NTHR, 1)
stein_fused(const float* __restrict__ V, const float* __restrict__ G,
            float* __restrict__ out)
{
    __shared__ SmemAll sm;
    int b = blockIdx.x, t = threadIdx.x;
    unsigned lsense = g_sense;   // snapshot (replay-safe)

    // ---- Phase A: Q partials, 4 tiles x 32 K-slices of 64 ----
    {
        int tile = b & 3, z = b >> 2;
        dot64w(&sm, V, G, g_part + z * NN, (tile >> 1) * 64, (tile & 1) * 64,
               z * 64, DD, 1.0f);
    }
    gbar(lsense);

    // ---- Phase B: reduce 32 partials -> P (blocks 0..31) ----
    {
        int gid = b * NTHR + t;
        if (gid < NN) {
            float s = 0.f;
            #pragma unroll
            for (int z = 0; z < ZSL; z++) s += g_part[z * NN + gid];
            g_P[gid] = s * (1.0f / 128.0f);
        }
    }
    gbar(lsense);

    // ---- Phase C: S halves = 128 * P P^T (blocks 64..71) ----
    if (b >= 64 && b < 72) {
        int id = b - 64;
        int khalf = id & 1, tile = id >> 1;
        dot64w(&sm, g_P, g_P, g_S2 + khalf * NN, (tile >> 1) * 64, (tile & 1) * 64,
               khalf * 64, NP, 128.0f);
    }
    gbar(lsense);

    // ---- Phase M: median of dMsd (block 0 only) ----
    if (b == 0) {
        int lane = t & 31, wid = t >> 5;
        if (t < 128) sm.m.sdiag[t] = g_S2[t * NP + t] + g_S2[NN + t * NP + t];
        __syncthreads();

        unsigned keys[32];
        {
            int i = t >> 2, j0 = (t & 3) * 32;
            float sdi = sm.m.sdiag[i];
            #pragma unroll 8
            for (int e = 0; e < 32; e++) {
                int j = j0 + e;
                float d = sdi + sm.m.sdiag[j]
                        - (g_S2[i*NP + j] + g_S2[NN + i*NP + j])
                        - (g_S2[j*NP + i] + g_S2[NN + j*NP + i]);
                keys[e] = f2key(d);
            }
        }

        unsigned hi_mask = 0u, hi_val = 0u, krank = 8192u;
        int mode = 0;   // 0 = continue, 1 = list-select, 2 = exact
        for (int p = 0; p < 4 && mode == 0; p++) {
            int shift = 24 - 8 * p;
            if (t < 256) sm.m.hist[t] = 0u;
            __syncthreads();
            #pragma unroll
            for (int e = 0; e < 32; e++) {
                unsigned key = keys[e];
                bool ok = (key & hi_mask) == hi_val;
                unsigned bin = ok ? ((key >> shift) & 255u) : 0xFFFFFFFFu;
                unsigned mm = __match_any_sync(0xFFFFFFFFu, bin);
                if (ok && ((int)(__ffs(mm) - 1) == lane))
                    atomicAdd(&sm.m.hist[bin], (unsigned)__popc(mm));
            }
            __syncthreads();
            // parallel scan of 256 bins (threads 0..255)
            if (t < 256) {
                unsigned v = sm.m.hist[t], incl = v;
                #pragma unroll
                for (int off = 1; off < 32; off <<= 1) {
                    unsigned nv = __shfl_up_sync(0xFFFFFFFFu, incl, off);
                    if (lane >= off) incl += nv;
                }
                if (lane == 31) sm.m.wsum[wid] = incl;
                __syncthreads();
                if (t < 8) {
                    unsigned w = sm.m.wsum[t], in2 = w;
                    #pragma unroll
                    for (int off = 1; off < 8; off <<= 1) {
                        unsigned nv = __shfl_up_sync(0xFFu, in2, off);
                        if (t >= off) in2 += nv;
                    }
                    sm.m.wsum[t] = in2 - w;
                }
                __syncthreads();
                unsigned excl = incl - v + sm.m.wsum[wid];
                if (excl <= krank && krank < excl + v) {
                    sm.m.sel[0] = (unsigned)t;
                    sm.m.sel[1] = krank - excl;
                    sm.m.sel[2] = v;
                }
            } else { __syncthreads(); __syncthreads(); }
            __syncthreads();
            hi_mask |= (0xFFu << shift);
            hi_val  |= (sm.m.sel[0] << shift);
            krank    = sm.m.sel[1];
            unsigned bc = sm.m.sel[2];
            if (shift == 0)       mode = 2;
            else if (bc <= 512u)  mode = 1;
            if (t == 0) sm.m.cnt = 0u;
            __syncthreads();
        }

        unsigned medkey = hi_val;
        if (mode == 1) {
            #pragma unroll
            for (int e = 0; e < 32; e++) {
                unsigned key = keys[e];
                if ((key & hi_mask) == hi_val) {
                    unsigned pos = atomicAdd(&sm.m.cnt, 1u);
                    if (pos < 512u) sm.m.list[pos] = key;
                }
            }
            __syncthreads();
            int L = (int)sm.m.cnt; if (L > 512) L = 512;
            for (int x = t; x < L; x += NTHR) {
                unsigned key = sm.m.list[x];
                unsigned less = 0, eq = 0;
                for (int j = 0; j < L; j++) {
                    unsigned kv = sm.m.list[j];
                    less += (kv < key);
                    eq   += (kv == key);
                }
                if (less <= krank && krank < less + eq) sm.m.sel[3] = key;
            }
            __syncthreads();
            medkey = sm.m.sel[3];
        }
        if (t == 0) {
            unsigned u = (medkey & 0x80000000u) ? (medkey ^ 0x80000000u) : ~medkey;
            float med = __uint_as_float(u);
            float h = (med * med) / 6.9314718f;   // ln(128)
            g_consts[0] = 0.5f / h;
            g_consts[1] = 1.0f / h;
        }
    }
    gbar(lsense);

    // ---- Phase EF: W rows (8 per block) + out = W @ G ----
    {
        int r0 = (b >> 3) * 8, cg = b & 7;
        float inv2h = g_consts[0], invh = g_consts[1];
        float* Wk = (float*)&sm.e.Wk4[0][0];
        float* Wb = (float*)&sm.e.Wb4[0][0];

        if (t < 128) sm.e.sd[t] = g_S2[t * NP + t] + g_S2[NN + t * NP + t];
        __syncthreads();

        // kern rows r0..r0+7 : 1024 entries, 2 per thread
        #pragma unroll
        for (int p = 0; p < 2; p++) {
            int idx = t + p * 512;
            int r = idx >> 7, j = idx & 127;
            int i = r0 + r;
            float d = sm.e.sd[i] + sm.e.sd[j]
                    - (g_S2[i*NP + j] + g_S2[NN + i*NP + j])
                    - (g_S2[j*NP + i] + g_S2[NN + j*NP + i]);
            Wk[r * 128 + j] = __expf(-d * inv2h);
        }
        __syncthreads();

        // rowsums: warps 0..7 reduce rows 0..7
        {
            int w = t >> 5, l = t & 31;
            if (w < 8) {
                float v = Wk[w*128 + l] + Wk[w*128 + l + 32]
                        + Wk[w*128 + l + 64] + Wk[w*128 + l + 96];
                #pragma unroll
                for (int off = 16; off > 0; off >>= 1)
                    v += __shfl_down_sync(0xFFFFFFFFu, v, off);
                if (l == 0) sm.e.rs[w] = v;
            }
        }
        __syncthreads();

        // kern @ P : j split into quarters across 4 thread groups
        {
            int c = t & 127, h4 = t >> 7;
            float acc8[8];
            #pragma unroll
            for (int r = 0; r < 8; r++) acc8[r] = 0.f;
            int jb0 = h4 * 8;                 // float4 groups (8 per quarter)
            #pragma unroll 4
            for (int j4 = jb0; j4 < jb0 + 8; j4++) {
                int j = 4 * j4;
                float p0 = g_P[(j    ) * NP + c];
                float p1 = g_P[(j + 1) * NP + c];
                float p2 = g_P[(j + 2) * NP + c];
                float p3 = g_P[(j + 3) * NP + c];
                #pragma unroll
                for (int r = 0; r < 8; r++) {
                    float4 w4 = sm.e.Wk4[r][j4];
                    acc8[r] += w4.x*p0 + w4.y*p1 + w4.z*p2 + w4.w*p3;
                }
            }
            #pragma unroll
            for (int r = 0; r < 8; r++) sm.e.pacc[h4][r][c] = acc8[r];
        }
        __syncthreads();

        // combine into Wb: 1024 entries, 2 per thread
        #pragma unroll
        for (int p = 0; p < 2; p++) {
            int idx = t + p * 512;
            int r = idx >> 7, c = idx & 127;
            int i = r0 + r;
            float a = sm.e.pacc[0][r][c] + sm.e.pacc[1][r][c]
                    + sm.e.pacc[2][r][c] + sm.e.pacc[3][r][c];
            Wb[r * 128 + c] = Wk[r * 128 + c]
                            + invh * (a - sm.e.rs[r] * g_P[i * NP + c]);
        }
        __syncthreads();

        // out: rows r0..r0+7 x cols cg*256..+255 ; thread does 4 rows
        {
            int c2 = cg * 256 + (t & 255);
            int rh = t >> 8;                  // 0 or 1
            int rb = rh * 4;
            float acc[4];
            #pragma unroll
            for (int r = 0; r < 4; r++) acc[r] = 0.f;
            #pragma unroll 4
            for (int j4 = 0; j4 < 32; j4++) {
                int j = 4 * j4;
                float g0 = G[(j    ) * DD + c2];
                float g1 = G[(j + 1) * DD + c2];
                float g2 = G[(j + 2) * DD + c2];
                float g3 = G[(j + 3) * DD + c2];
                #pragma unroll
                for (int r = 0; r < 4; r++) {
                    float4 w4 = sm.e.Wb4[rb + r][j4];
                    acc[r] += w4.x*g0 + w4.y*g1 + w4.z*g2 + w4.w*g3;
                }
            }
            #pragma unroll
            for (int r = 0; r < 4; r++) out[(r0 + rb + r) * DD + c2] = acc[r];
        }
    }
}

extern "C" void kernel_launch(void* const* d_in, const int* in_sizes, int n_in,
                              void* d_out, int out_size)
{
    const float* var  = (const float*)d_in[0];
    const float* grad = (const float*)d_in[1];
    float* out = (float*)d_out;
    stein_fused<<<NBLK, NTHR>>>(var, grad, out);
}

// round 6
// speedup vs baseline: 1.3042x; 1.2708x over previous
#include <cuda_runtime.h>
#include <math.h>

#define NP   128
#define DD   2048
#define NN   16384
#define NBLK 128
#define NTHR 512
#define ZSL  32      // K slices in phase A

// ---------------- scratch (no allocations allowed) ----------------
__device__ float    g_part[ZSL*NN];   // phase-A partials of Q = V G^T (2 MB)
__device__ float    g_Q[NN];          // Q = V G^T
__device__ float    g_S[NN];          // S = Q Q^T / 128 (symmetric)
__device__ unsigned g_cnt[256];       // 8 sub-counters, 128B apart
__device__ unsigned g_root[32];
__device__ unsigned g_epoch[32];      // monotonic barrier epoch

// ---------------- shared memory union ----------------
struct SmemAll {
    union {
        struct { float4 As4[64][17]; float4 Bs4[64][17]; } a;            // 34.8 KB GEMM
        struct { float4 pc[256][4]; } r;                                  // combine (aliases a)
        struct { float sd[128];                                           // shared w/ e.sd
                 unsigned hist[256]; unsigned wsum[8];
                 unsigned sel[4]; unsigned cnt; unsigned list[512]; } m;  // median
        struct { float sd[128]; float rs[8];
                 float4 Wk4[8][32]; float pacc[4][8][128];
                 float4 Wb4[8][32]; } e;                                  // ~25 KB EF
    };
};

// ---------------- acquire/release helpers ----------------
__device__ __forceinline__ unsigned ld_acq(unsigned* p) {
    unsigned v;
    asm volatile("ld.acquire.gpu.u32 %0, [%1];" : "=r"(v) : "l"(p) : "memory");
    return v;
}
__device__ __forceinline__ void st_rel(unsigned* p, unsigned v) {
    asm volatile("st.release.gpu.u32 [%0], %1;" :: "l"(p), "r"(v) : "memory");
}

// ---------------- grid barrier: tree arrival, monotonic epoch ----------------
// v = absolute epoch this barrier completes (base + i). 16 blocks per sub-counter.
__device__ __forceinline__ void gbar(unsigned v, int b) {
    __syncthreads();
    if (threadIdx.x == 0) {
        __threadfence();
        unsigned r = atomicAdd(&g_cnt[(b & 7) * 32], 1u);
        if (r == 16u * v - 1u) {
            unsigned r2 = atomicAdd(&g_root[0], 1u);
            if (r2 == 8u * v - 1u) st_rel(&g_epoch[0], v);
        }
        while (ld_acq(&g_epoch[0]) < v) __nanosleep(32);
        __threadfence();
    }
    __syncthreads();
}

// ============================================================
// 64x64 tile of A x B^T over nch K-chunks of 64, 512 threads.
// kh = t>>8 splits each chunk's K 32+32; combine once at the end.
// ============================================================
__device__ __forceinline__ void dot64w(SmemAll* sm,
                                       const float* __restrict__ A,
                                       const float* __restrict__ B,
                                       float* __restrict__ C,
                                       int arow0, int brow0, int k0, int nch,
                                       int K, float scale)
{
    int t = threadIdx.x;
    int tx = t & 15, ty = (t >> 4) & 15, kh = t >> 8;
    const float4* A4 = (const float4*)A;
    const float4* B4 = (const float4*)B;
    int K4 = K >> 2;
    float* Asf = (float*)&sm->a.As4[0][0];   // row stride 68 floats
    float* Bsf = (float*)&sm->a.Bs4[0][0];

    float acc[4][4];
    #pragma unroll
    for (int i = 0; i < 4; i++)
        #pragma unroll
        for (int j = 0; j < 4; j++) acc[i][j] = 0.f;

    for (int ch = 0; ch < nch; ch++) {
        int q0 = (k0 >> 2) + ch * 16;
        __syncthreads();
        #pragma unroll
        for (int p = 0; p < 4; p++) {
            int idx = t + p * 512;                  // 0..2047
            int mat = idx >> 10;                    // 0=A, 1=B
            int rr = (idx >> 4) & 63, q = idx & 15;
            const float4* S4 = mat ? B4 : A4;
            float* D = mat ? Bsf : Asf;
            int row0 = mat ? brow0 : arow0;
            float4 v = S4[(row0 + rr) * K4 + q0 + q];
            int cp = (((rr >> 2) ^ q) << 2) | (rr & 3);
            int kb = 4 * q;
            D[(kb    ) * 68 + cp] = v.x;
            D[(kb + 1) * 68 + cp] = v.y;
            D[(kb + 2) * 68 + cp] = v.z;
            D[(kb + 3) * 68 + cp] = v.w;
        }
        __syncthreads();
        int kb0 = kh * 32;
        #pragma unroll 8
        for (int k = kb0; k < kb0 + 32; k++) {
            int s = k >> 2;
            float4 av = sm->a.As4[k][ty ^ s];
            float4 bv = sm->a.Bs4[k][tx ^ s];
            acc[0][0] += av.x*bv.x; acc[0][1] += av.x*bv.y; acc[0][2] += av.x*bv.z; acc[0][3] += av.x*bv.w;
            acc[1][0] += av.y*bv.x; acc[1][1] += av.y*bv.y; acc[1][2] += av.y*bv.z; acc[1][3] += av.y*bv.w;
            acc[2][0] += av.z*bv.x; acc[2][1] += av.z*bv.y; acc[2][2] += av.z*bv.z; acc[2][3] += av.z*bv.w;
            acc[3][0] += av.w*bv.x; acc[3][1] += av.w*bv.y; acc[3][2] += av.w*bv.z; acc[3][3] += av.w*bv.w;
        }
    }
    __syncthreads();                            // done reading As/Bs (pc aliases)
    int slot = ty * 16 + tx;
    if (kh == 1) {
        #pragma unroll
        for (int i = 0; i < 4; i++)
            sm->r.pc[slot][i] = make_float4(acc[i][0], acc[i][1], acc[i][2], acc[i][3]);
    }
    __syncthreads();
    if (kh == 0) {
        #pragma unroll
        for (int i = 0; i < 4; i++) {
            float4 o = sm->r.pc[slot][i];
            o.x = (o.x + acc[i][0]) * scale;
            o.y = (o.y + acc[i][1]) * scale;
            o.z = (o.z + acc[i][2]) * scale;
            o.w = (o.w + acc[i][3]) * scale;
            *(float4*)&C[(arow0 + 4*ty + i) * NP + brow0 + 4*tx] = o;
        }
    }
}

__device__ __forceinline__ unsigned f2key(float d) {
    unsigned u = __float_as_uint(d);
    return (u & 0x80000000u) ? ~u : (u | 0x80000000u);
}

// ==================================================================
__global__ void __launch_bounds__(NTHR, 1)
stein_fused(const float* __restrict__ V, const float* __restrict__ G,
            float* __restrict__ out)
{
    __shared__ SmemAll sm;
    int b = blockIdx.x, t = threadIdx.x;
    int lane = t & 31, wid = t >> 5;
    unsigned base = ld_acq(&g_epoch[0]);   // settled epoch from previous launch

    // ---- Phase A: Q partials, 4 tiles x 32 K-slices of 64 ----
    {
        int tile = b & 3, z = b >> 2;
        dot64w(&sm, V, G, g_part + z * NN, (tile >> 1) * 64, (tile & 1) * 64,
               z * 64, 1, DD, 1.0f);
    }
    gbar(base + 1, b);

    // ---- Phase B: reduce 32 partials -> Q (blocks 0..31) ----
    if (b < 32) {
        int gid = b * NTHR + t;
        float s = 0.f;
        #pragma unroll
        for (int z = 0; z < ZSL; z++) s += g_part[z * NN + gid];
        g_Q[gid] = s;
    }
    gbar(base + 2, b);

    // ---- Phase C: S = Q Q^T / 128 (blocks 0..3, one 64x64 tile each, 2 chunks) ----
    if (b < 4) {
        dot64w(&sm, g_Q, g_Q, g_S, ((b >> 1) & 1) * 64, (b & 1) * 64,
               0, 2, NP, 1.0f / 128.0f);
    }
    gbar(base + 3, b);

    // ================= Phase M (replicated per block) =================
    if (t < 128) sm.m.sd[t] = g_S[t * NP + t];
    __syncthreads();

    unsigned keys[32];
    {
        int i = t >> 2, j0 = (t & 3) * 32;
        float sdi = sm.m.sd[i];
        const float4* S4 = (const float4*)(g_S + i * NP + j0);
        #pragma unroll
        for (int e4 = 0; e4 < 8; e4++) {
            float4 s4 = S4[e4];
            int j = j0 + 4 * e4;
            keys[4*e4+0] = f2key((sdi + sm.m.sd[j+0]) - (s4.x + s4.x));
            keys[4*e4+1] = f2key((sdi + sm.m.sd[j+1]) - (s4.y + s4.y));
            keys[4*e4+2] = f2key((sdi + sm.m.sd[j+2]) - (s4.z + s4.z));
            keys[4*e4+3] = f2key((sdi + sm.m.sd[j+3]) - (s4.w + s4.w));
        }
    }

    unsigned hi_mask = 0u, hi_val = 0u, krank = 8192u;
    int mode = 0;   // 0 = continue, 1 = list-select, 2 = exact
    for (int p = 0; p < 4 && mode == 0; p++) {
        int shift = 24 - 8 * p;
        if (t < 256) sm.m.hist[t] = 0u;
        __syncthreads();
        #pragma unroll
        for (int e = 0; e < 32; e++) {
            unsigned key = keys[e];
            bool ok = (key & hi_mask) == hi_val;
            unsigned bin = ok ? ((key >> shift) & 255u) : 0xFFFFFFFFu;
            unsigned mm = __match_any_sync(0xFFFFFFFFu, bin);
            if (ok && ((int)(__ffs(mm) - 1) == lane))
                atomicAdd(&sm.m.hist[bin], (unsigned)__popc(mm));
        }
        __syncthreads();
        unsigned v = 0, incl = 0;
        if (t < 256) {
            v = sm.m.hist[t]; incl = v;
            #pragma unroll
            for (int off = 1; off < 32; off <<= 1) {
                unsigned nv = __shfl_up_sync(0xFFFFFFFFu, incl, off);
                if (lane >= off) incl += nv;
            }
            if (lane == 31) sm.m.wsum[wid] = incl;
        }
        __syncthreads();
        if (t < 8) {
            unsigned w = sm.m.wsum[t], in2 = w;
            #pragma unroll
            for (int off = 1; off < 8; off <<= 1) {
                unsigned nv = __shfl_up_sync(0xFFu, in2, off);
                if (t >= off) in2 += nv;
            }
            sm.m.wsum[t] = in2 - w;
        }
        __syncthreads();
        if (t < 256) {
            unsigned excl = incl - v + sm.m.wsum[wid];
            if (excl <= krank && krank < excl + v) {
                sm.m.sel[0] = (unsigned)t;
                sm.m.sel[1] = krank - excl;
                sm.m.sel[2] = v;
            }
        }
        __syncthreads();
        hi_mask |= (0xFFu << shift);
        hi_val  |= (sm.m.sel[0] << shift);
        krank    = sm.m.sel[1];
        unsigned bc = sm.m.sel[2];
        if (shift == 0)       mode = 2;
        else if (bc <= 512u)  mode = 1;
        if (t == 0) sm.m.cnt = 0u;
        __syncthreads();
    }

    unsigned medkey = hi_val;
    if (mode == 1) {
        #pragma unroll
        for (int e = 0; e < 32; e++) {
            unsigned key = keys[e];
            if ((key & hi_mask) == hi_val) {
                unsigned pos = atomicAdd(&sm.m.cnt, 1u);
                if (pos < 512u) sm.m.list[pos] = key;
            }
        }
        __syncthreads();
        int L = (int)sm.m.cnt; if (L > 512) L = 512;
        for (int x = t; x < L; x += NTHR) {
            unsigned key = sm.m.list[x];
            unsigned less = 0, eq = 0;
            for (int j = 0; j < L; j++) {
                unsigned kv = sm.m.list[j];
                less += (kv < key);
                eq   += (kv == key);
            }
            if (less <= krank && krank < less + eq) sm.m.sel[3] = key;
        }
        __syncthreads();
        medkey = sm.m.sel[3];
    }
    float inv2h, invh128;
    {
        unsigned u = (medkey & 0x80000000u) ? (medkey ^ 0x80000000u) : ~medkey;
        float med = __uint_as_float(u);
        float h = (med * med) / 6.9314718f;   // ln(128)
        inv2h = 0.5f / h;
        invh128 = 1.0f / (h * 128.0f);
    }
    __syncthreads();    // m -> e union switch (sd at same offset, preserved)

    // ================= Phase EF =================
    {
        int r0 = (b >> 3) * 8, cg = b & 7;
        float* Wk = (float*)&sm.e.Wk4[0][0];
        float* Wb = (float*)&sm.e.Wb4[0][0];

        // kern rows r0..r0+7 (2 per thread)
        #pragma unroll
        for (int p = 0; p < 2; p++) {
            int idx = t + p * 512;
            int r = idx >> 7, j = idx & 127;
            int i = r0 + r;
            float s = g_S[i * NP + j];
            float d = (sm.e.sd[i] + sm.e.sd[j]) - (s + s);
            Wk[r * 128 + j] = __expf(-d * inv2h);
        }
        __syncthreads();

        // rowsums: warps 0..7 reduce rows 0..7
        if (wid < 8) {
            float v = Wk[wid*128 + lane] + Wk[wid*128 + lane + 32]
                    + Wk[wid*128 + lane + 64] + Wk[wid*128 + lane + 96];
            #pragma unroll
            for (int off = 16; off > 0; off >>= 1)
                v += __shfl_down_sync(0xFFFFFFFFu, v, off);
            if (lane == 0) sm.e.rs[wid] = v;
        }
        __syncthreads();

        // kern @ Q : j split into quarters across 4 thread groups
        {
            int c = t & 127, h4 = t >> 7;
            float acc8[8];
            #pragma unroll
            for (int r = 0; r < 8; r++) acc8[r] = 0.f;
            int jb0 = h4 * 8;
            #pragma unroll 4
            for (int j4 = jb0; j4 < jb0 + 8; j4++) {
                int j = 4 * j4;
                float q0 = g_Q[(j    ) * NP + c];
                float q1 = g_Q[(j + 1) * NP + c];
                float q2 = g_Q[(j + 2) * NP + c];
                float q3 = g_Q[(j + 3) * NP + c];
                #pragma unroll
                for (int r = 0; r < 8; r++) {
                    float4 w4 = sm.e.Wk4[r][j4];
                    acc8[r] += w4.x*q0 + w4.y*q1 + w4.z*q2 + w4.w*q3;
                }
            }
            #pragma unroll
            for (int r = 0; r < 8; r++) sm.e.pacc[h4][r][c] = acc8[r];
        }
        __syncthreads();

        // combine into Wb
        #pragma unroll
        for (int p = 0; p < 2; p++) {
            int idx = t + p * 512;
            int r = idx >> 7, c = idx & 127;
            int i = r0 + r;
            float a = sm.e.pacc[0][r][c] + sm.e.pacc[1][r][c]
                    + sm.e.pacc[2][r][c] + sm.e.pacc[3][r][c];
            Wb[r * 128 + c] = Wk[r * 128 + c]
                            + invh128 * (a - sm.e.rs[r] * g_Q[i * NP + c]);
        }
        __syncthreads();

        // out: rows r0..r0+7 x cols cg*256..+255 ; each thread 4 rows
        {
            int c2 = cg * 256 + (t & 255);
            int rb = (t >> 8) * 4;
            float acc[4];
            #pragma unroll
            for (int r = 0; r < 4; r++) acc[r] = 0.f;
            #pragma unroll 4
            for (int j4 = 0; j4 < 32; j4++) {
                int j = 4 * j4;
                float g0 = G[(j    ) * DD + c2];
                float g1 = G[(j + 1) * DD + c2];
                float g2 = G[(j + 2) * DD + c2];
                float g3 = G[(j + 3) * DD + c2];
                #pragma unroll
                for (int r = 0; r < 4; r++) {
                    float4 w4 = sm.e.Wb4[rb + r][j4];
                    acc[r] += w4.x*g0 + w4.y*g1 + w4.z*g2 + w4.w*g3;
                }
            }
            #pragma unroll
            for (int r = 0; r < 4; r++) out[(r0 + rb + r) * DD + c2] = acc[r];
        }
    }
}

extern "C" void kernel_launch(void* const* d_in, const int* in_sizes, int n_in,
                              void* d_out, int out_size)
{
    const float* var  = (const float*)d_in[0];
    const float* grad = (const float*)d_in[1];
    float* out = (float*)d_out;
    stein_fused<<<NBLK, NTHR>>>(var, grad, out);
}

// round 7
// speedup vs baseline: 1.3558x; 1.0396x over previous
#include <cuda_runtime.h>
#include <math.h>

#define NP   128
#define DD   2048
#define NN   16384
#define NBLK 148
#define NTHR 512
#define ZSL  32      // K slices in phase A

// ---------------- scratch (no allocations allowed) ----------------
__device__ float    g_part[ZSL*NN];   // phase-A partials of Q = V G^T (2 MB)
__device__ float    g_Q[NN];          // Q = V G^T
__device__ float    g_S2[2*NN];       // S = Q Q^T / 128 in two K-halves (sum them)
__device__ unsigned g_cnt[128];       // 4 leaf counters, 128B apart
__device__ unsigned g_root[32];
__device__ unsigned g_epoch[32];      // monotonic barrier epoch

// ---------------- shared memory union ----------------
struct SmemAll {
    union {
        struct { float4 As4[64][17]; float4 Bs4[64][17]; } a;            // 34.8 KB GEMM
        struct { float4 pc[256][4]; } r;                                  // combine (aliases a)
        struct { float pacc[4][128]; } bred;                              // phase B combine
        struct { float sd[128];
                 unsigned hist[256]; unsigned wsum[8];
                 unsigned sel[4]; unsigned cnt; unsigned list[512]; } m;  // median
        struct { float sd[128]; float rs[8];
                 float4 Wk4[8][32]; float pacc[4][8][128];
                 float4 Wb4[8][32]; } e;                                  // ~25 KB EF
    };
};

// ---------------- acquire/release helpers ----------------
__device__ __forceinline__ unsigned ld_acq(unsigned* p) {
    unsigned v;
    asm volatile("ld.acquire.gpu.u32 %0, [%1];" : "=r"(v) : "l"(p) : "memory");
    return v;
}
__device__ __forceinline__ void st_rel(unsigned* p, unsigned v) {
    asm volatile("st.release.gpu.u32 [%0], %1;" :: "l"(p), "r"(v) : "memory");
}

// ---------------- grid barrier: 4-leaf tree, monotonic epoch ----------------
// v = absolute epoch this barrier completes. 37 blocks per leaf (148 = 4*37).
__device__ __forceinline__ void gbar(unsigned v, int b) {
    __syncthreads();
    if (threadIdx.x == 0) {
        __threadfence();
        unsigned r = atomicAdd(&g_cnt[(b & 3) * 32], 1u);
        if (r == 37u * v - 1u) {
            unsigned r2 = atomicAdd(&g_root[0], 1u);
            if (r2 == 4u * v - 1u) st_rel(&g_epoch[0], v);
        }
        while (ld_acq(&g_epoch[0]) < v) __nanosleep(16);
        __threadfence();
    }
    __syncthreads();
}

// ============================================================
// 64x64 tile of A x B^T over one 64-wide K chunk, 512 threads.
// kh = t>>8 splits K 32+32; smem combine at the end.
// ============================================================
__device__ __forceinline__ void dot64w(SmemAll* sm,
                                       const float* __restrict__ A,
                                       const float* __restrict__ B,
                                       float* __restrict__ C,
                                       int arow0, int brow0, int k0,
                                       int K, float scale)
{
    int t = threadIdx.x;
    int tx = t & 15, ty = (t >> 4) & 15, kh = t >> 8;
    const float4* A4 = (const float4*)A;
    const float4* B4 = (const float4*)B;
    int K4 = K >> 2, q0 = k0 >> 2;
    float* Asf = (float*)&sm->a.As4[0][0];   // row stride 68 floats
    float* Bsf = (float*)&sm->a.Bs4[0][0];

    float acc[4][4];
    #pragma unroll
    for (int i = 0; i < 4; i++)
        #pragma unroll
        for (int j = 0; j < 4; j++) acc[i][j] = 0.f;

    #pragma unroll
    for (int p = 0; p < 4; p++) {
        int idx = t + p * 512;                  // 0..2047
        int mat = idx >> 10;                    // 0=A, 1=B
        int rr = (idx >> 4) & 63, q = idx & 15;
        const float4* S4 = mat ? B4 : A4;
        float* D = mat ? Bsf : Asf;
        int row0 = mat ? brow0 : arow0;
        float4 v = S4[(row0 + rr) * K4 + q0 + q];
        int cp = (((rr >> 2) ^ q) << 2) | (rr & 3);
        int kb = 4 * q;
        D[(kb    ) * 68 + cp] = v.x;
        D[(kb + 1) * 68 + cp] = v.y;
        D[(kb + 2) * 68 + cp] = v.z;
        D[(kb + 3) * 68 + cp] = v.w;
    }
    __syncthreads();
    int kb0 = kh * 32;
    #pragma unroll 8
    for (int k = kb0; k < kb0 + 32; k++) {
        int s = k >> 2;
        float4 av = sm->a.As4[k][ty ^ s];
        float4 bv = sm->a.Bs4[k][tx ^ s];
        acc[0][0] += av.x*bv.x; acc[0][1] += av.x*bv.y; acc[0][2] += av.x*bv.z; acc[0][3] += av.x*bv.w;
        acc[1][0] += av.y*bv.x; acc[1][1] += av.y*bv.y; acc[1][2] += av.y*bv.z; acc[1][3] += av.y*bv.w;
        acc[2][0] += av.z*bv.x; acc[2][1] += av.z*bv.y; acc[2][2] += av.z*bv.z; acc[2][3] += av.z*bv.w;
        acc[3][0] += av.w*bv.x; acc[3][1] += av.w*bv.y; acc[3][2] += av.w*bv.z; acc[3][3] += av.w*bv.w;
    }
    __syncthreads();                            // done reading As/Bs (pc aliases)
    int slot = ty * 16 + tx;
    if (kh == 1) {
        #pragma unroll
        for (int i = 0; i < 4; i++)
            sm->r.pc[slot][i] = make_float4(acc[i][0], acc[i][1], acc[i][2], acc[i][3]);
    }
    __syncthreads();
    if (kh == 0) {
        #pragma unroll
        for (int i = 0; i < 4; i++) {
            float4 o = sm->r.pc[slot][i];
            o.x = (o.x + acc[i][0]) * scale;
            o.y = (o.y + acc[i][1]) * scale;
            o.z = (o.z + acc[i][2]) * scale;
            o.w = (o.w + acc[i][3]) * scale;
            *(float4*)&C[(arow0 + 4*ty + i) * NP + brow0 + 4*tx] = o;
        }
    }
}

__device__ __forceinline__ unsigned f2key(float d) {
    unsigned u = __float_as_uint(d);
    return (u & 0x80000000u) ? ~u : (u | 0x80000000u);
}

// ==================================================================
__global__ void __launch_bounds__(NTHR, 1)
stein_fused(const float* __restrict__ V, const float* __restrict__ G,
            float* __restrict__ out)
{
    __shared__ SmemAll sm;
    int b = blockIdx.x, t = threadIdx.x;
    int lane = t & 31, wid = t >> 5;
    unsigned base = ld_acq(&g_epoch[0]);   // settled epoch from previous launch

    // ---- Phase A: Q partials, 4 tiles x 32 K-slices of 64 (blocks 0..127) ----
    if (b < 128) {
        int tile = b & 3, z = b >> 2;
        dot64w(&sm, V, G, g_part + z * NN, (tile >> 1) * 64, (tile & 1) * 64,
               z * 64, DD, 1.0f);
    }
    gbar(base + 1, b);

    // ---- Phase B: reduce 32 partials -> Q (blocks 0..127, 128 elems each) ----
    if (b < 128) {
        int e0 = b * 128 + (t & 127);
        int qy = t >> 7;                       // quarter 0..3
        float s = 0.f;
        #pragma unroll
        for (int z = 0; z < 8; z++) s += g_part[(qy * 8 + z) * NN + e0];
        sm.bred.pacc[qy][t & 127] = s;
        __syncthreads();
        if (t < 128)
            g_Q[b * 128 + t] = sm.bred.pacc[0][t] + sm.bred.pacc[1][t]
                             + sm.bred.pacc[2][t] + sm.bred.pacc[3][t];
    }
    gbar(base + 2, b);

    // ---- Phase C: S halves = Q Q^T / 128 (blocks 0..7) ----
    if (b < 8) {
        int khalf = b & 1, tile = b >> 1;
        dot64w(&sm, g_Q, g_Q, g_S2 + khalf * NN, (tile >> 1) * 64, (tile & 1) * 64,
               khalf * 64, NP, 1.0f / 128.0f);
    }
    gbar(base + 3, b);

    if (b >= 128) return;   // barrier-only blocks exit

    // ================= Phase M (replicated per block) =================
    if (t < 128) sm.m.sd[t] = g_S2[t * NP + t] + g_S2[NN + t * NP + t];
    __syncthreads();

    unsigned keys[32];
    {
        int i = t >> 2, j0 = (t & 3) * 32;
        float sdi = sm.m.sd[i];
        const float4* Sa4 = (const float4*)(g_S2 + i * NP + j0);
        const float4* Sb4 = (const float4*)(g_S2 + NN + i * NP + j0);
        #pragma unroll
        for (int e4 = 0; e4 < 8; e4++) {
            float4 sa = Sa4[e4];
            float4 sb = Sb4[e4];
            int j = j0 + 4 * e4;
            float s0 = sa.x + sb.x, s1 = sa.y + sb.y;
            float s2 = sa.z + sb.z, s3 = sa.w + sb.w;
            keys[4*e4+0] = f2key((sdi + sm.m.sd[j+0]) - (s0 + s0));
            keys[4*e4+1] = f2key((sdi + sm.m.sd[j+1]) - (s1 + s1));
            keys[4*e4+2] = f2key((sdi + sm.m.sd[j+2]) - (s2 + s2));
            keys[4*e4+3] = f2key((sdi + sm.m.sd[j+3]) - (s3 + s3));
        }
    }

    unsigned hi_mask = 0u, hi_val = 0u, krank = 8192u;
    int mode = 0;   // 0 = continue, 1 = list-select, 2 = exact
    for (int p = 0; p < 4 && mode == 0; p++) {
        int shift = 24 - 8 * p;
        if (t < 256) sm.m.hist[t] = 0u;
        __syncthreads();
        #pragma unroll
        for (int e = 0; e < 32; e++) {
            unsigned key = keys[e];
            bool ok = (key & hi_mask) == hi_val;
            unsigned bin = ok ? ((key >> shift) & 255u) : 0xFFFFFFFFu;
            unsigned mm = __match_any_sync(0xFFFFFFFFu, bin);
            if (ok && ((int)(__ffs(mm) - 1) == lane))
                atomicAdd(&sm.m.hist[bin], (unsigned)__popc(mm));
        }
        __syncthreads();
        unsigned v = 0, incl = 0;
        if (t < 256) {
            v = sm.m.hist[t]; incl = v;
            #pragma unroll
            for (int off = 1; off < 32; off <<= 1) {
                unsigned nv = __shfl_up_sync(0xFFFFFFFFu, incl, off);
                if (lane >= off) incl += nv;
            }
            if (lane == 31) sm.m.wsum[wid] = incl;
        }
        __syncthreads();
        if (t < 8) {
            unsigned w = sm.m.wsum[t], in2 = w;
            #pragma unroll
            for (int off = 1; off < 8; off <<= 1) {
                unsigned nv = __shfl_up_sync(0xFFu, in2, off);
                if (t >= off) in2 += nv;
            }
            sm.m.wsum[t] = in2 - w;
        }
        __syncthreads();
        if (t < 256) {
            unsigned excl = incl - v + sm.m.wsum[wid];
            if (excl <= krank && krank < excl + v) {
                sm.m.sel[0] = (unsigned)t;
                sm.m.sel[1] = krank - excl;
                sm.m.sel[2] = v;
            }
        }
        __syncthreads();
        hi_mask |= (0xFFu << shift);
        hi_val  |= (sm.m.sel[0] << shift);
        krank    = sm.m.sel[1];
        unsigned bc = sm.m.sel[2];
        if (shift == 0)       mode = 2;
        else if (bc <= 512u)  mode = 1;
        if (t == 0) sm.m.cnt = 0u;
        __syncthreads();
    }

    unsigned medkey = hi_val;
    if (mode == 1) {
        #pragma unroll
        for (int e = 0; e < 32; e++) {
            unsigned key = keys[e];
            if ((key & hi_mask) == hi_val) {
                unsigned pos = atomicAdd(&sm.m.cnt, 1u);
                if (pos < 512u) sm.m.list[pos] = key;
            }
        }
        __syncthreads();
        int L = (int)sm.m.cnt; if (L > 512) L = 512;
        for (int x = t; x < L; x += NTHR) {
            unsigned key = sm.m.list[x];
            unsigned less = 0, eq = 0;
            for (int j = 0; j < L; j++) {
                unsigned kv = sm.m.list[j];
                less += (kv < key);
                eq   += (kv == key);
            }
            if (less <= krank && krank < less + eq) sm.m.sel[3] = key;
        }
        __syncthreads();
        medkey = sm.m.sel[3];
    }
    float inv2h, invh128;
    {
        unsigned u = (medkey & 0x80000000u) ? (medkey ^ 0x80000000u) : ~medkey;
        float med = __uint_as_float(u);
        float h = (med * med) / 6.9314718f;   // ln(128)
        inv2h = 0.5f / h;
        invh128 = 1.0f / (h * 128.0f);
    }
    __syncthreads();    // m -> e union switch (sd at same offset, preserved)

    // ================= Phase EF =================
    {
        int r0 = (b >> 3) * 8, cg = b & 7;
        float* Wk = (float*)&sm.e.Wk4[0][0];
        float* Wb = (float*)&sm.e.Wb4[0][0];

        // kern rows r0..r0+7 (2 per thread)
        #pragma unroll
        for (int p = 0; p < 2; p++) {
            int idx = t + p * 512;
            int r = idx >> 7, j = idx & 127;
            int i = r0 + r;
            float s = g_S2[i * NP + j] + g_S2[NN + i * NP + j];
            float d = (sm.e.sd[i] + sm.e.sd[j]) - (s + s);
            Wk[r * 128 + j] = __expf(-d * inv2h);
        }
        __syncthreads();

        // rowsums: warps 0..7 reduce rows 0..7
        if (wid < 8) {
            float v = Wk[wid*128 + lane] + Wk[wid*128 + lane + 32]
                    + Wk[wid*128 + lane + 64] + Wk[wid*128 + lane + 96];
            #pragma unroll
            for (int off = 16; off > 0; off >>= 1)
                v += __shfl_down_sync(0xFFFFFFFFu, v, off);
            if (lane == 0) sm.e.rs[wid] = v;
        }
        __syncthreads();

        // kern @ Q : j split into quarters across 4 thread groups
        {
            int c = t & 127, h4 = t >> 7;
            float acc8[8];
            #pragma unroll
            for (int r = 0; r < 8; r++) acc8[r] = 0.f;
            int jb0 = h4 * 8;
            #pragma unroll 4
            for (int j4 = jb0; j4 < jb0 + 8; j4++) {
                int j = 4 * j4;
                float q0 = g_Q[(j    ) * NP + c];
                float q1 = g_Q[(j + 1) * NP + c];
                float q2 = g_Q[(j + 2) * NP + c];
                float q3 = g_Q[(j + 3) * NP + c];
                #pragma unroll
                for (int r = 0; r < 8; r++) {
                    float4 w4 = sm.e.Wk4[r][j4];
                    acc8[r] += w4.x*q0 + w4.y*q1 + w4.z*q2 + w4.w*q3;
                }
            }
            #pragma unroll
            for (int r = 0; r < 8; r++) sm.e.pacc[h4][r][c] = acc8[r];
        }
        __syncthreads();

        // combine into Wb
        #pragma unroll
        for (int p = 0; p < 2; p++) {
            int idx = t + p * 512;
            int r = idx >> 7, c = idx & 127;
            int i = r0 + r;
            float a = sm.e.pacc[0][r][c] + sm.e.pacc[1][r][c]
                    + sm.e.pacc[2][r][c] + sm.e.pacc[3][r][c];
            Wb[r * 128 + c] = Wk[r * 128 + c]
                            + invh128 * (a - sm.e.rs[r] * g_Q[i * NP + c]);
        }
        __syncthreads();

        // out: rows r0..r0+7 x cols cg*256..+255 ; each thread 4 rows
        {
            int c2 = cg * 256 + (t & 255);
            int rb = (t >> 8) * 4;
            float acc[4];
            #pragma unroll
            for (int r = 0; r < 4; r++) acc[r] = 0.f;
            #pragma unroll 4
            for (int j4 = 0; j4 < 32; j4++) {
                int j = 4 * j4;
                float g0 = G[(j    ) * DD + c2];
                float g1 = G[(j + 1) * DD + c2];
                float g2 = G[(j + 2) * DD + c2];
                float g3 = G[(j + 3) * DD + c2];
                #pragma unroll
                for (int r = 0; r < 4; r++) {
                    float4 w4 = sm.e.Wb4[rb + r][j4];
                    acc[r] += w4.x*g0 + w4.y*g1 + w4.z*g2 + w4.w*g3;
                }
            }
            #pragma unroll
            for (int r = 0; r < 4; r++) out[(r0 + rb + r) * DD + c2] = acc[r];
        }
    }
}

extern "C" void kernel_launch(void* const* d_in, const int* in_sizes, int n_in,
                              void* d_out, int out_size)
{
    const float* var  = (const float*)d_in[0];
    const float* grad = (const float*)d_in[1];
    float* out = (float*)d_out;
    stein_fused<<<NBLK, NTHR>>>(var, grad, out);
}

// round 8
// speedup vs baseline: 1.5993x; 1.1796x over previous
#include <cuda_runtime.h>
#include <math.h>

#define NP   128
#define DD   2048
#define NN   16384
#define NBLK 148
#define NTHR 512
#define ZSL  32      // K slices in phase A

// ---------------- scratch (no allocations allowed) ----------------
__device__ float    g_part[ZSL*NN];   // phase-A partials; reused as prewarm dump
__device__ float    g_Q[NN];          // Q = V G^T
__device__ float    g_S4[4*NN];       // S = Q Q^T / 128 in four K-quarters (sum them)
__device__ unsigned g_cnt[128];       // 4 leaf counters, 128B apart
__device__ unsigned g_root[32];
__device__ unsigned g_epoch[32];      // monotonic barrier epoch

// ---------------- shared memory union ----------------
struct SmemAll {
    union {
        struct { float4 As4[64][17]; float4 Bs4[64][17]; } a;            // 34.8 KB GEMM
        struct { float4 pc[256][4]; } r;                                  // combine (aliases a)
        struct { float pacc[4][128]; } bred;                              // phase B combine
        struct { float sd[128];
                 unsigned hist[256]; unsigned wsum[8]; unsigned sel[4]; } m;  // median
        struct { float sd[128]; float rs[8];
                 float4 Wk4[8][32]; float pacc[4][8][128];
                 float4 Wb4[8][32]; } e;                                  // ~25 KB EF
    };
};

// ---------------- acquire/release helpers ----------------
__device__ __forceinline__ unsigned ld_acq(unsigned* p) {
    unsigned v;
    asm volatile("ld.acquire.gpu.u32 %0, [%1];" : "=r"(v) : "l"(p) : "memory");
    return v;
}
__device__ __forceinline__ void st_rel(unsigned* p, unsigned v) {
    asm volatile("st.release.gpu.u32 [%0], %1;" :: "l"(p), "r"(v) : "memory");
}

// ---------------- grid barrier: 4-leaf tree, monotonic epoch ----------------
__device__ __forceinline__ void gbar(unsigned v, int b) {
    __syncthreads();
    if (threadIdx.x == 0) {
        __threadfence();
        unsigned r = atomicAdd(&g_cnt[(b & 3) * 32], 1u);
        if (r == 37u * v - 1u) {
            unsigned r2 = atomicAdd(&g_root[0], 1u);
            if (r2 == 4u * v - 1u) st_rel(&g_epoch[0], v);
        }
        while (ld_acq(&g_epoch[0]) < v) __nanosleep(16);
        __threadfence();
    }
    __syncthreads();
}

// ============================================================
// 64x64 tile of A x B^T over one 64-wide K chunk, 512 threads.
// ============================================================
__device__ __forceinline__ void dot64w(SmemAll* sm,
                                       const float* __restrict__ A,
                                       const float* __restrict__ B,
                                       float* __restrict__ C,
                                       int arow0, int brow0, int k0,
                                       int K, float scale)
{
    int t = threadIdx.x;
    int tx = t & 15, ty = (t >> 4) & 15, kh = t >> 8;
    const float4* A4 = (const float4*)A;
    const float4* B4 = (const float4*)B;
    int K4 = K >> 2, q0 = k0 >> 2;
    float* Asf = (float*)&sm->a.As4[0][0];   // row stride 68 floats
    float* Bsf = (float*)&sm->a.Bs4[0][0];

    float acc[4][4];
    #pragma unroll
    for (int i = 0; i < 4; i++)
        #pragma unroll
        for (int j = 0; j < 4; j++) acc[i][j] = 0.f;

    #pragma unroll
    for (int p = 0; p < 4; p++) {
        int idx = t + p * 512;                  // 0..2047
        int mat = idx >> 10;                    // 0=A, 1=B
        int rr = (idx >> 4) & 63, q = idx & 15;
        const float4* S4 = mat ? B4 : A4;
        float* D = mat ? Bsf : Asf;
        int row0 = mat ? brow0 : arow0;
        float4 v = S4[(row0 + rr) * K4 + q0 + q];
        int cp = (((rr >> 2) ^ q) << 2) | (rr & 3);
        int kb = 4 * q;
        D[(kb    ) * 68 + cp] = v.x;
        D[(kb + 1) * 68 + cp] = v.y;
        D[(kb + 2) * 68 + cp] = v.z;
        D[(kb + 3) * 68 + cp] = v.w;
    }
    __syncthreads();
    int kb0 = kh * 32;
    #pragma unroll 8
    for (int k = kb0; k < kb0 + 32; k++) {
        int s = k >> 2;
        float4 av = sm->a.As4[k][ty ^ s];
        float4 bv = sm->a.Bs4[k][tx ^ s];
        acc[0][0] += av.x*bv.x; acc[0][1] += av.x*bv.y; acc[0][2] += av.x*bv.z; acc[0][3] += av.x*bv.w;
        acc[1][0] += av.y*bv.x; acc[1][1] += av.y*bv.y; acc[1][2] += av.y*bv.z; acc[1][3] += av.y*bv.w;
        acc[2][0] += av.z*bv.x; acc[2][1] += av.z*bv.y; acc[2][2] += av.z*bv.z; acc[2][3] += av.z*bv.w;
        acc[3][0] += av.w*bv.x; acc[3][1] += av.w*bv.y; acc[3][2] += av.w*bv.z; acc[3][3] += av.w*bv.w;
    }
    __syncthreads();                            // done reading As/Bs (pc aliases)
    int slot = ty * 16 + tx;
    if (kh == 1) {
        #pragma unroll
        for (int i = 0; i < 4; i++)
            sm->r.pc[slot][i] = make_float4(acc[i][0], acc[i][1], acc[i][2], acc[i][3]);
    }
    __syncthreads();
    if (kh == 0) {
        #pragma unroll
        for (int i = 0; i < 4; i++) {
            float4 o = sm->r.pc[slot][i];
            o.x = (o.x + acc[i][0]) * scale;
            o.y = (o.y + acc[i][1]) * scale;
            o.z = (o.z + acc[i][2]) * scale;
            o.w = (o.w + acc[i][3]) * scale;
            *(float4*)&C[(arow0 + 4*ty + i) * NP + brow0 + 4*tx] = o;
        }
    }
}

// ============================================================
// 64x64 tile of A x B^T over one 32-wide K chunk (phase C quarters).
// ============================================================
__device__ __forceinline__ void dot64q(SmemAll* sm,
                                       const float* __restrict__ A,
                                       const float* __restrict__ B,
                                       float* __restrict__ C,
                                       int arow0, int brow0, int k0,
                                       int K, float scale)
{
    int t = threadIdx.x;
    int tx = t & 15, ty = (t >> 4) & 15, kh = t >> 8;
    const float4* A4 = (const float4*)A;
    const float4* B4 = (const float4*)B;
    int K4 = K >> 2, q0 = k0 >> 2;
    float* Asf = (float*)&sm->a.As4[0][0];
    float* Bsf = (float*)&sm->a.Bs4[0][0];

    float acc[4][4];
    #pragma unroll
    for (int i = 0; i < 4; i++)
        #pragma unroll
        for (int j = 0; j < 4; j++) acc[i][j] = 0.f;

    #pragma unroll
    for (int p = 0; p < 2; p++) {
        int idx = t + p * 512;                  // 0..1023
        int mat = idx >> 9;                     // 0=A, 1=B
        int rr = (idx >> 3) & 63, q = idx & 7;
        const float4* S4 = mat ? B4 : A4;
        float* D = mat ? Bsf : Asf;
        int row0 = mat ? brow0 : arow0;
        float4 v = S4[(row0 + rr) * K4 + q0 + q];
        int cp = (((rr >> 2) ^ q) << 2) | (rr & 3);
        int kb = 4 * q;
        D[(kb    ) * 68 + cp] = v.x;
        D[(kb + 1) * 68 + cp] = v.y;
        D[(kb + 2) * 68 + cp] = v.z;
        D[(kb + 3) * 68 + cp] = v.w;
    }
    __syncthreads();
    int kb0 = kh * 16;
    #pragma unroll 8
    for (int k = kb0; k < kb0 + 16; k++) {
        int s = k >> 2;
        float4 av = sm->a.As4[k][ty ^ s];
        float4 bv = sm->a.Bs4[k][tx ^ s];
        acc[0][0] += av.x*bv.x; acc[0][1] += av.x*bv.y; acc[0][2] += av.x*bv.z; acc[0][3] += av.x*bv.w;
        acc[1][0] += av.y*bv.x; acc[1][1] += av.y*bv.y; acc[1][2] += av.y*bv.z; acc[1][3] += av.y*bv.w;
        acc[2][0] += av.z*bv.x; acc[2][1] += av.z*bv.y; acc[2][2] += av.z*bv.z; acc[2][3] += av.z*bv.w;
        acc[3][0] += av.w*bv.x; acc[3][1] += av.w*bv.y; acc[3][2] += av.w*bv.z; acc[3][3] += av.w*bv.w;
    }
    __syncthreads();
    int slot = ty * 16 + tx;
    if (kh == 1) {
        #pragma unroll
        for (int i = 0; i < 4; i++)
            sm->r.pc[slot][i] = make_float4(acc[i][0], acc[i][1], acc[i][2], acc[i][3]);
    }
    __syncthreads();
    if (kh == 0) {
        #pragma unroll
        for (int i = 0; i < 4; i++) {
            float4 o = sm->r.pc[slot][i];
            o.x = (o.x + acc[i][0]) * scale;
            o.y = (o.y + acc[i][1]) * scale;
            o.z = (o.z + acc[i][2]) * scale;
            o.w = (o.w + acc[i][3]) * scale;
            *(float4*)&C[(arow0 + 4*ty + i) * NP + brow0 + 4*tx] = o;
        }
    }
}

__device__ __forceinline__ unsigned f2key(float d) {
    unsigned u = __float_as_uint(d);
    return (u & 0x80000000u) ? ~u : (u | 0x80000000u);
}

// ==================================================================
__global__ void __launch_bounds__(NTHR, 1)
stein_fused(const float* __restrict__ V, const float* __restrict__ G,
            float* __restrict__ out)
{
    __shared__ SmemAll sm;
    int b = blockIdx.x, t = threadIdx.x;
    int lane = t & 31, wid = t >> 5;
    unsigned base = ld_acq(&g_epoch[0]);   // settled epoch from previous launch

    // ---- Phase A: Q partials, 4 tiles x 32 K-slices of 64 (blocks 0..127) ----
    if (b < 128) {
        int tile = b & 3, z = b >> 2;
        dot64w(&sm, V, G, g_part + z * NN, (tile >> 1) * 64, (tile & 1) * 64,
               z * 64, DD, 1.0f);
    }
    gbar(base + 1, b);

    // ---- Phase B: reduce 32 partials -> Q (blocks 0..127, 128 elems each) ----
    if (b < 128) {
        int e0 = b * 128 + (t & 127);
        int qy = t >> 7;                       // quarter 0..3
        float s = 0.f;
        #pragma unroll
        for (int z = 0; z < 8; z++) s += g_part[(qy * 8 + z) * NN + e0];
        sm.bred.pacc[qy][t & 127] = s;
        __syncthreads();
        if (t < 128)
            g_Q[b * 128 + t] = sm.bred.pacc[0][t] + sm.bred.pacc[1][t]
                             + sm.bred.pacc[2][t] + sm.bred.pacc[3][t];
    }
    gbar(base + 2, b);

    // ---- Phase C: S quarters = Q Q^T / 128 (blocks 0..15); others prewarm L1 ----
    if (b < 16) {
        int khq = b & 3, tile = b >> 2;
        dot64q(&sm, g_Q, g_Q, g_S4 + khq * NN, (tile >> 1) * 64, (tile & 1) * 64,
               khq * 32, NP, 1.0f / 128.0f);
    } else if (b < 128) {
        // warm L1 with this block's EF working set (G column slice + Q)
        float acc = 0.f;
        if (t < 256) {
            int c2 = (b & 7) * 256 + t;
            #pragma unroll 8
            for (int j = 0; j < 128; j++) acc += G[j * DD + c2];
        } else {
            int c = t & 127;
            #pragma unroll 8
            for (int j = 0; j < 128; j++) acc += g_Q[j * NP + c];
        }
        g_part[b * NTHR + t] = acc;            // keep loads alive (scratch, dead data)
    }
    gbar(base + 3, b);

    if (b >= 128) return;   // barrier-only blocks exit

    // ================= Phase M (replicated per block) =================
    if (t < 128)
        sm.m.sd[t] = g_S4[t * NP + t] + g_S4[NN + t * NP + t]
                   + g_S4[2*NN + t * NP + t] + g_S4[3*NN + t * NP + t];
    __syncthreads();

    unsigned keys[32];
    {
        int i = t >> 2, j0 = (t & 3) * 32;
        float sdi = sm.m.sd[i];
        const float4* S0 = (const float4*)(g_S4 + 0*NN + i * NP + j0);
        const float4* S1 = (const float4*)(g_S4 + 1*NN + i * NP + j0);
        const float4* S2 = (const float4*)(g_S4 + 2*NN + i * NP + j0);
        const float4* S3 = (const float4*)(g_S4 + 3*NN + i * NP + j0);
        #pragma unroll
        for (int e4 = 0; e4 < 8; e4++) {
            float4 a0 = S0[e4], a1 = S1[e4], a2 = S2[e4], a3 = S3[e4];
            int j = j0 + 4 * e4;
            float s0 = a0.x + a1.x + a2.x + a3.x;
            float s1 = a0.y + a1.y + a2.y + a3.y;
            float s2 = a0.z + a1.z + a2.z + a3.z;
            float s3 = a0.w + a1.w + a2.w + a3.w;
            keys[4*e4+0] = f2key((sdi + sm.m.sd[j+0]) - (s0 + s0));
            keys[4*e4+1] = f2key((sdi + sm.m.sd[j+1]) - (s1 + s1));
            keys[4*e4+2] = f2key((sdi + sm.m.sd[j+2]) - (s2 + s2));
            keys[4*e4+3] = f2key((sdi + sm.m.sd[j+3]) - (s3 + s3));
        }
    }

    unsigned hi_mask = 0u, hi_val = 0u, krank = 8192u;
    unsigned medkey = 0u;
    bool done = false;
    for (int p = 0; p < 4 && !done; p++) {
        int shift = 24 - 8 * p;
        if (t < 256) sm.m.hist[t] = 0u;
        __syncthreads();
        if (p == 0) {
            // all keys active: warp-aggregate (keys cluster into few exponent bins)
            #pragma unroll
            for (int e = 0; e < 32; e++) {
                unsigned bin = keys[e] >> 24;
                unsigned mm = __match_any_sync(0xFFFFFFFFu, bin);
                if ((int)(__ffs(mm) - 1) == lane)
                    atomicAdd(&sm.m.hist[bin], (unsigned)__popc(mm));
            }
        } else {
            // few active keys: plain predicated atomics
            #pragma unroll
            for (int e = 0; e < 32; e++) {
                unsigned key = keys[e];
                if ((key & hi_mask) == hi_val)
                    atomicAdd(&sm.m.hist[(key >> shift) & 255u], 1u);
            }
        }
        __syncthreads();
        unsigned v = 0, incl = 0;
        if (t < 256) {
            v = sm.m.hist[t]; incl = v;
            #pragma unroll
            for (int off = 1; off < 32; off <<= 1) {
                unsigned nv = __shfl_up_sync(0xFFFFFFFFu, incl, off);
                if (lane >= off) incl += nv;
            }
            if (lane == 31) sm.m.wsum[wid] = incl;
        }
        __syncthreads();
        if (t < 8) {
            unsigned w = sm.m.wsum[t], in2 = w;
            #pragma unroll
            for (int off = 1; off < 8; off <<= 1) {
                unsigned nv = __shfl_up_sync(0xFFu, in2, off);
                if (t >= off) in2 += nv;
            }
            sm.m.wsum[t] = in2 - w;
        }
        __syncthreads();
        if (t < 256) {
            unsigned excl = incl - v + sm.m.wsum[wid];
            if (excl <= krank && krank < excl + v) {
                sm.m.sel[0] = (unsigned)t;
                sm.m.sel[1] = krank - excl;
                sm.m.sel[2] = v;
            }
        }
        __syncthreads();
        hi_mask |= (0xFFu << shift);
        hi_val  |= (sm.m.sel[0] << shift);
        krank    = sm.m.sel[1];
        unsigned bc = sm.m.sel[2];
        __syncthreads();
        if (shift == 0) {
            medkey = hi_val;
            done = true;
        } else if (bc == 1u) {
            // unique key in selected bucket: it IS the median
            #pragma unroll
            for (int e = 0; e < 32; e++)
                if ((keys[e] & hi_mask) == hi_val) sm.m.sel[3] = keys[e];
            __syncthreads();
            medkey = sm.m.sel[3];
            done = true;
        }
    }

    float inv2h, invh128;
    {
        unsigned u = (medkey & 0x80000000u) ? (medkey ^ 0x80000000u) : ~medkey;
        float med = __uint_as_float(u);
        float h = (med * med) / 6.9314718f;   // ln(128)
        inv2h = 0.5f / h;
        invh128 = 1.0f / (h * 128.0f);
    }
    __syncthreads();    // m -> e union switch (sd at same offset, preserved)

    // ================= Phase EF =================
    {
        int r0 = (b >> 3) * 8, cg = b & 7;
        float* Wk = (float*)&sm.e.Wk4[0][0];
        float* Wb = (float*)&sm.e.Wb4[0][0];

        // kern rows r0..r0+7 (2 per thread)
        #pragma unroll
        for (int p = 0; p < 2; p++) {
            int idx = t + p * 512;
            int r = idx >> 7, j = idx & 127;
            int i = r0 + r;
            float s = g_S4[i * NP + j] + g_S4[NN + i * NP + j]
                    + g_S4[2*NN + i * NP + j] + g_S4[3*NN + i * NP + j];
            float d = (sm.e.sd[i] + sm.e.sd[j]) - (s + s);
            Wk[r * 128 + j] = __expf(-d * inv2h);
        }
        __syncthreads();

        // rowsums: warps 0..7 reduce rows 0..7
        if (wid < 8) {
            float v = Wk[wid*128 + lane] + Wk[wid*128 + lane + 32]
                    + Wk[wid*128 + lane + 64] + Wk[wid*128 + lane + 96];
            #pragma unroll
            for (int off = 16; off > 0; off >>= 1)
                v += __shfl_down_sync(0xFFFFFFFFu, v, off);
            if (lane == 0) sm.e.rs[wid] = v;
        }
        __syncthreads();

        // kern @ Q : j split into quarters across 4 thread groups
        {
            int c = t & 127, h4 = t >> 7;
            float acc8[8];
            #pragma unroll
            for (int r = 0; r < 8; r++) acc8[r] = 0.f;
            int jb0 = h4 * 8;
            #pragma unroll 4
            for (int j4 = jb0; j4 < jb0 + 8; j4++) {
                int j = 4 * j4;
                float q0 = g_Q[(j    ) * NP + c];
                float q1 = g_Q[(j + 1) * NP + c];
                float q2 = g_Q[(j + 2) * NP + c];
                float q3 = g_Q[(j + 3) * NP + c];
                #pragma unroll
                for (int r = 0; r < 8; r++) {
                    float4 w4 = sm.e.Wk4[r][j4];
                    acc8[r] += w4.x*q0 + w4.y*q1 + w4.z*q2 + w4.w*q3;
                }
            }
            #pragma unroll
            for (int r = 0; r < 8; r++) sm.e.pacc[h4][r][c] = acc8[r];
        }
        __syncthreads();

        // combine into Wb
        #pragma unroll
        for (int p = 0; p < 2; p++) {
            int idx = t + p * 512;
            int r = idx >> 7, c = idx & 127;
            int i = r0 + r;
            float a = sm.e.pacc[0][r][c] + sm.e.pacc[1][r][c]
                    + sm.e.pacc[2][r][c] + sm.e.pacc[3][r][c];
            Wb[r * 128 + c] = Wk[r * 128 + c]
                            + invh128 * (a - sm.e.rs[r] * g_Q[i * NP + c]);
        }
        __syncthreads();

        // out: rows r0..r0+7 x cols cg*256..+255 ; each thread 4 rows
        {
            int c2 = cg * 256 + (t & 255);
            int rb = (t >> 8) * 4;
            float acc[4];
            #pragma unroll
            for (int r = 0; r < 4; r++) acc[r] = 0.f;
            #pragma unroll 4
            for (int j4 = 0; j4 < 32; j4++) {
                int j = 4 * j4;
                float g0 = G[(j    ) * DD + c2];
                float g1 = G[(j + 1) * DD + c2];
                float g2 = G[(j + 2) * DD + c2];
                float g3 = G[(j + 3) * DD + c2];
                #pragma unroll
                for (int r = 0; r < 4; r++) {
                    float4 w4 = sm.e.Wb4[rb + r][j4];
                    acc[r] += w4.x*g0 + w4.y*g1 + w4.z*g2 + w4.w*g3;
                }
            }
            #pragma unroll
            for (int r = 0; r < 4; r++) out[(r0 + rb + r) * DD + c2] = acc[r];
        }
    }
}

extern "C" void kernel_launch(void* const* d_in, const int* in_sizes, int n_in,
                              void* d_out, int out_size)
{
    const float* var  = (const float*)d_in[0];
    const float* grad = (const float*)d_in[1];
    float* out = (float*)d_out;
    stein_fused<<<NBLK, NTHR>>>(var, grad, out);
}

// round 10
// speedup vs baseline: 1.7799x; 1.1129x over previous
#include <cuda_runtime.h>
#include <math.h>

#define NP   128
#define DD   2048
#define NN   16384
#define NBLK 148
#define NTHR 512
#define ZSL  32      // K slices in phase A

// ---------------- scratch (no allocations allowed) ----------------
__device__ float    g_part[ZSL*NN];   // phase-A partials; prewarm dump elsewhere
__device__ float    g_dump[NBLK*NTHR];
__device__ float    g_Q[NN];          // Q = V G^T
__device__ float    g_S4[4*NN];       // S = Q Q^T / 128 in four K-quarters (sum them)
__device__ unsigned g_cnt[16*32];     // 16 leaf counters, 128B apart
__device__ unsigned g_root[32];
__device__ unsigned g_epoch[32];      // monotonic barrier epoch

// ---------------- shared memory union ----------------
struct SmemAll {
    union {
        struct { float4 As4[64][17]; float4 Bs4[64][17]; } a;            // 34.8 KB GEMM
        struct { float4 pc[256][4]; } r;                                  // combine (aliases a)
        struct { float pacc[4][128]; } bred;                              // phase B combine
        struct { float sd[128];
                 unsigned hist[256]; unsigned wsum[8]; unsigned sel[4]; } m;  // median
        struct { float sd[128]; float rs[8];
                 float4 Wk4[8][32]; float pacc[4][8][128];
                 float4 Wb4[8][32]; } e;                                  // ~25 KB EF
    };
};

// ---------------- acquire/release helpers ----------------
__device__ __forceinline__ unsigned ld_acq(unsigned* p) {
    unsigned v;
    asm volatile("ld.acquire.gpu.u32 %0, [%1];" : "=r"(v) : "l"(p) : "memory");
    return v;
}
__device__ __forceinline__ void st_rel(unsigned* p, unsigned v) {
    asm volatile("st.release.gpu.u32 [%0], %1;" :: "l"(p), "r"(v) : "memory");
}

// ---------------- grid barrier: 16-leaf tree, monotonic epoch ----------------
// 148 blocks: leaves 0..3 get 10 blocks, leaves 4..15 get 9.
__device__ __forceinline__ void gbar(unsigned v, int b) {
    __syncthreads();
    if (threadIdx.x == 0) {
        __threadfence();
        int leaf = b & 15;
        unsigned leafsz = (leaf < 4) ? 10u : 9u;
        unsigned r = atomicAdd(&g_cnt[leaf * 32], 1u);
        if (r == leafsz * v - 1u) {
            unsigned r2 = atomicAdd(&g_root[0], 1u);
            if (r2 == 16u * v - 1u) st_rel(&g_epoch[0], v);
        }
        while (ld_acq(&g_epoch[0]) < v) __nanosleep(16);
        __threadfence();
    }
    __syncthreads();
}

// ============================================================
// 64x64 tile of A x B^T over one 64-wide K chunk, 512 threads.
// ============================================================
__device__ __forceinline__ void dot64w(SmemAll* sm,
                                       const float* __restrict__ A,
                                       const float* __restrict__ B,
                                       float* __restrict__ C,
                                       int arow0, int brow0, int k0,
                                       int K, float scale)
{
    int t = threadIdx.x;
    int tx = t & 15, ty = (t >> 4) & 15, kh = t >> 8;
    const float4* A4 = (const float4*)A;
    const float4* B4 = (const float4*)B;
    int K4 = K >> 2, q0 = k0 >> 2;
    float* Asf = (float*)&sm->a.As4[0][0];   // row stride 68 floats
    float* Bsf = (float*)&sm->a.Bs4[0][0];

    float acc[4][4];
    #pragma unroll
    for (int i = 0; i < 4; i++)
        #pragma unroll
        for (int j = 0; j < 4; j++) acc[i][j] = 0.f;

    #pragma unroll
    for (int p = 0; p < 4; p++) {
        int idx = t + p * 512;                  // 0..2047
        int mat = idx >> 10;                    // 0=A, 1=B
        int rr = (idx >> 4) & 63, q = idx & 15;
        const float4* S4 = mat ? B4 : A4;
        float* D = mat ? Bsf : Asf;
        int row0 = mat ? brow0 : arow0;
        float4 v = S4[(row0 + rr) * K4 + q0 + q];
        int cp = (((rr >> 2) ^ q) << 2) | (rr & 3);
        int kb = 4 * q;
        D[(kb    ) * 68 + cp] = v.x;
        D[(kb + 1) * 68 + cp] = v.y;
        D[(kb + 2) * 68 + cp] = v.z;
        D[(kb + 3) * 68 + cp] = v.w;
    }
    __syncthreads();
    int kb0 = kh * 32;
    #pragma unroll 8
    for (int k = kb0; k < kb0 + 32; k++) {
        int s = k >> 2;
        float4 av = sm->a.As4[k][ty ^ s];
        float4 bv = sm->a.Bs4[k][tx ^ s];
        acc[0][0] += av.x*bv.x; acc[0][1] += av.x*bv.y; acc[0][2] += av.x*bv.z; acc[0][3] += av.x*bv.w;
        acc[1][0] += av.y*bv.x; acc[1][1] += av.y*bv.y; acc[1][2] += av.y*bv.z; acc[1][3] += av.y*bv.w;
        acc[2][0] += av.z*bv.x; acc[2][1] += av.z*bv.y; acc[2][2] += av.z*bv.z; acc[2][3] += av.z*bv.w;
        acc[3][0] += av.w*bv.x; acc[3][1] += av.w*bv.y; acc[3][2] += av.w*bv.z; acc[3][3] += av.w*bv.w;
    }
    __syncthreads();                            // done reading As/Bs (pc aliases)
    int slot = ty * 16 + tx;
    if (kh == 1) {
        #pragma unroll
        for (int i = 0; i < 4; i++)
            sm->r.pc[slot][i] = make_float4(acc[i][0], acc[i][1], acc[i][2], acc[i][3]);
    }
    __syncthreads();
    if (kh == 0) {
        #pragma unroll
        for (int i = 0; i < 4; i++) {
            float4 o = sm->r.pc[slot][i];
            o.x = (o.x + acc[i][0]) * scale;
            o.y = (o.y + acc[i][1]) * scale;
            o.z = (o.z + acc[i][2]) * scale;
            o.w = (o.w + acc[i][3]) * scale;
            *(float4*)&C[(arow0 + 4*ty + i) * NP + brow0 + 4*tx] = o;
        }
    }
}

// ============================================================
// 64x64 tile of A x B^T over one 32-wide K chunk (phase C quarters).
// ============================================================
__device__ __forceinline__ void dot64q(SmemAll* sm,
                                       const float* __restrict__ A,
                                       const float* __restrict__ B,
                                       float* __restrict__ C,
                                       int arow0, int brow0, int k0,
                                       int K, float scale)
{
    int t = threadIdx.x;
    int tx = t & 15, ty = (t >> 4) & 15, kh = t >> 8;
    const float4* A4 = (const float4*)A;
    const float4* B4 = (const float4*)B;
    int K4 = K >> 2, q0 = k0 >> 2;
    float* Asf = (float*)&sm->a.As4[0][0];
    float* Bsf = (float*)&sm->a.Bs4[0][0];

    float acc[4][4];
    #pragma unroll
    for (int i = 0; i < 4; i++)
        #pragma unroll
        for (int j = 0; j < 4; j++) acc[i][j] = 0.f;

    #pragma unroll
    for (int p = 0; p < 2; p++) {
        int idx = t + p * 512;                  // 0..1023
        int mat = idx >> 9;                     // 0=A, 1=B
        int rr = (idx >> 3) & 63, q = idx & 7;
        const float4* S4 = mat ? B4 : A4;
        float* D = mat ? Bsf : Asf;
        int row0 = mat ? brow0 : arow0;
        float4 v = S4[(row0 + rr) * K4 + q0 + q];
        int cp = (((rr >> 2) ^ q) << 2) | (rr & 3);
        int kb = 4 * q;
        D[(kb    ) * 68 + cp] = v.x;
        D[(kb + 1) * 68 + cp] = v.y;
        D[(kb + 2) * 68 + cp] = v.z;
        D[(kb + 3) * 68 + cp] = v.w;
    }
    __syncthreads();
    int kb0 = kh * 16;
    #pragma unroll 8
    for (int k = kb0; k < kb0 + 16; k++) {
        int s = k >> 2;
        float4 av = sm->a.As4[k][ty ^ s];
        float4 bv = sm->a.Bs4[k][tx ^ s];
        acc[0][0] += av.x*bv.x; acc[0][1] += av.x*bv.y; acc[0][2] += av.x*bv.z; acc[0][3] += av.x*bv.w;
        acc[1][0] += av.y*bv.x; acc[1][1] += av.y*bv.y; acc[1][2] += av.y*bv.z; acc[1][3] += av.y*bv.w;
        acc[2][0] += av.z*bv.x; acc[2][1] += av.z*bv.y; acc[2][2] += av.z*bv.z; acc[2][3] += av.z*bv.w;
        acc[3][0] += av.w*bv.x; acc[3][1] += av.w*bv.y; acc[3][2] += av.w*bv.z; acc[3][3] += av.w*bv.w;
    }
    __syncthreads();
    int slot = ty * 16 + tx;
    if (kh == 1) {
        #pragma unroll
        for (int i = 0; i < 4; i++)
            sm->r.pc[slot][i] = make_float4(acc[i][0], acc[i][1], acc[i][2], acc[i][3]);
    }
    __syncthreads();
    if (kh == 0) {
        #pragma unroll
        for (int i = 0; i < 4; i++) {
            float4 o = sm->r.pc[slot][i];
            o.x = (o.x + acc[i][0]) * scale;
            o.y = (o.y + acc[i][1]) * scale;
            o.z = (o.z + acc[i][2]) * scale;
            o.w = (o.w + acc[i][3]) * scale;
            *(float4*)&C[(arow0 + 4*ty + i) * NP + brow0 + 4*tx] = o;
        }
    }
}

__device__ __forceinline__ unsigned f2key(float d) {
    unsigned u = __float_as_uint(d);
    return (u & 0x80000000u) ? ~u : (u | 0x80000000u);
}

#define KSENT 0xFFFFFFFFu
#define ZKEY  0x80000000u   // f2key(0.0f)

// ==================================================================
__global__ void __launch_bounds__(NTHR, 1)
stein_fused(const float* __restrict__ V, const float* __restrict__ G,
            float* __restrict__ out)
{
    __shared__ SmemAll sm;
    int b = blockIdx.x, t = threadIdx.x;
    int lane = t & 31, wid = t >> 5;
    unsigned base = ld_acq(&g_epoch[0]);   // settled epoch from previous launch

    // ---- Phase A: Q partials, 4 tiles x 32 K-slices of 64 (blocks 0..127) ----
    if (b < 128) {
        int tile = b & 3, z = b >> 2;
        dot64w(&sm, V, G, g_part + z * NN, (tile >> 1) * 64, (tile & 1) * 64,
               z * 64, DD, 1.0f);
    }
    gbar(base + 1, b);

    // ---- Phase B: reduce 32 partials -> Q (blocks 0..127, 128 elems each) ----
    if (b < 128) {
        int e0 = b * 128 + (t & 127);
        int qy = t >> 7;                       // quarter 0..3
        float s = 0.f;
        #pragma unroll
        for (int z = 0; z < 8; z++) s += g_part[(qy * 8 + z) * NN + e0];
        sm.bred.pacc[qy][t & 127] = s;
        __syncthreads();
        if (t < 128)
            g_Q[b * 128 + t] = sm.bred.pacc[0][t] + sm.bred.pacc[1][t]
                             + sm.bred.pacc[2][t] + sm.bred.pacc[3][t];
    }
    gbar(base + 2, b);

    // ---- Phase C: S quarters = Q Q^T / 128 (blocks 0..15); others prewarm L1 ----
    if (b < 16) {
        int khq = b & 3, tile = b >> 2;
        dot64q(&sm, g_Q, g_Q, g_S4 + khq * NN, (tile >> 1) * 64, (tile & 1) * 64,
               khq * 32, NP, 1.0f / 128.0f);
    } else if (b < 128) {
        // warm L1 with this block's EF working set (G column slice + Q)
        float acc = 0.f;
        if (t < 256) {
            int c2 = (b & 7) * 256 + t;
            #pragma unroll 8
            for (int j = 0; j < 128; j++) acc += G[j * DD + c2];
        } else {
            int c = t & 127;
            #pragma unroll 8
            for (int j = 0; j < 128; j++) acc += g_Q[j * NP + c];
        }
        g_dump[b * NTHR + t] = acc;            // keep loads alive (dead data)
    }
    gbar(base + 3, b);

    if (b >= 128) return;   // barrier-only blocks exit

    // ========== Phase M (replicated; symmetric: j>i weight 2, diag 128 zeros) ==========
    if (t < 128)
        sm.m.sd[t] = g_S4[t * NP + t] + g_S4[NN + t * NP + t]
                   + g_S4[2*NN + t * NP + t] + g_S4[3*NN + t * NP + t];
    __syncthreads();

    unsigned keys[32];
    {
        int i = t >> 2, j0q = (t & 3) * 32;
        float sdi = sm.m.sd[i];
        const float4* S0 = (const float4*)(g_S4 + 0*NN + i * NP + j0q);
        const float4* S1 = (const float4*)(g_S4 + 1*NN + i * NP + j0q);
        const float4* S2 = (const float4*)(g_S4 + 2*NN + i * NP + j0q);
        const float4* S3 = (const float4*)(g_S4 + 3*NN + i * NP + j0q);
        #pragma unroll
        for (int e4 = 0; e4 < 8; e4++) {
            int j = j0q + 4 * e4;
            if (j + 3 > i) {
                float4 a0 = S0[e4], a1 = S1[e4], a2 = S2[e4], a3 = S3[e4];
                float s0 = a0.x + a1.x + a2.x + a3.x;
                float s1 = a0.y + a1.y + a2.y + a3.y;
                float s2 = a0.z + a1.z + a2.z + a3.z;
                float s3 = a0.w + a1.w + a2.w + a3.w;
                keys[4*e4+0] = (j+0 > i) ? f2key((sdi + sm.m.sd[j+0]) - (s0 + s0)) : KSENT;
                keys[4*e4+1] = (j+1 > i) ? f2key((sdi + sm.m.sd[j+1]) - (s1 + s1)) : KSENT;
                keys[4*e4+2] = (j+2 > i) ? f2key((sdi + sm.m.sd[j+2]) - (s2 + s2)) : KSENT;
                keys[4*e4+3] = (j+3 > i) ? f2key((sdi + sm.m.sd[j+3]) - (s3 + s3)) : KSENT;
            } else {
                keys[4*e4+0] = KSENT; keys[4*e4+1] = KSENT;
                keys[4*e4+2] = KSENT; keys[4*e4+3] = KSENT;
            }
        }
    }

    unsigned hi_mask = 0u, hi_val = 0u, krank = 8192u;
    for (int p = 0; p < 4; p++) {
        int shift = 24 - 8 * p;
        if (t < 256) sm.m.hist[t] = 0u;
        __syncthreads();
        if (p == 0) {
            // all keys active: warp-aggregate, weight 2 each; sentinels land in bin 255
            // (real keys never reach bin 255: d ~ O(1e4) -> top byte ~0xC5)
            #pragma unroll
            for (int e = 0; e < 32; e++) {
                unsigned bin = keys[e] >> 24;
                unsigned mm = __match_any_sync(0xFFFFFFFFu, bin);
                if ((int)(__ffs(mm) - 1) == lane)
                    atomicAdd(&sm.m.hist[bin], 2u * (unsigned)__popc(mm));
            }
            if (t == 0) atomicAdd(&sm.m.hist[ZKEY >> 24], 128u);   // diag zeros
        } else {
            #pragma unroll
            for (int e = 0; e < 32; e++) {
                unsigned key = keys[e];
                if ((key & hi_mask) == hi_val)
                    atomicAdd(&sm.m.hist[(key >> shift) & 255u], 2u);
            }
            if (t == 0 && (ZKEY & hi_mask) == hi_val)
                atomicAdd(&sm.m.hist[(ZKEY >> shift) & 255u], 128u);
        }
        __syncthreads();
        unsigned v = 0, incl = 0;
        if (t < 256) {
            v = sm.m.hist[t]; incl = v;
            #pragma unroll
            for (int off = 1; off < 32; off <<= 1) {
                unsigned nv = __shfl_up_sync(0xFFFFFFFFu, incl, off);
                if (lane >= off) incl += nv;
            }
            if (lane == 31) sm.m.wsum[wid] = incl;
        }
        __syncthreads();
        if (t < 8) {
            unsigned w = sm.m.wsum[t], in2 = w;
            #pragma unroll
            for (int off = 1; off < 8; off <<= 1) {
                unsigned nv = __shfl_up_sync(0xFFu, in2, off);
                if (t >= off) in2 += nv;
            }
            sm.m.wsum[t] = in2 - w;
        }
        __syncthreads();
        if (t < 256) {
            unsigned excl = incl - v + sm.m.wsum[wid];
            if (excl <= krank && krank < excl + v) {
                sm.m.sel[0] = (unsigned)t;
                sm.m.sel[1] = krank - excl;
            }
        }
        __syncthreads();
        hi_mask |= (0xFFu << shift);
        hi_val  |= (sm.m.sel[0] << shift);
        krank    = sm.m.sel[1];
        __syncthreads();
    }
    unsigned medkey = hi_val;

    float inv2h, invh128;
    {
        unsigned u = (medkey & 0x80000000u) ? (medkey ^ 0x80000000u) : ~medkey;
        float med = __uint_as_float(u);
        float h = (med * med) / 6.9314718f;   // ln(128)
        inv2h = 0.5f / h;
        invh128 = 1.0f / (h * 128.0f);
    }
    __syncthreads();    // m -> e union switch (sd at same offset, preserved)

    // ================= Phase EF =================
    {
        int r0 = (b >> 3) * 8, cg = b & 7;
        float* Wk = (float*)&sm.e.Wk4[0][0];
        float* Wb = (float*)&sm.e.Wb4[0][0];

        // kern rows r0..r0+7 (2 per thread)
        #pragma unroll
        for (int p = 0; p < 2; p++) {
            int idx = t + p * 512;
            int r = idx >> 7, j = idx & 127;
            int i = r0 + r;
            float s = g_S4[i * NP + j] + g_S4[NN + i * NP + j]
                    + g_S4[2*NN + i * NP + j] + g_S4[3*NN + i * NP + j];
            float d = (sm.e.sd[i] + sm.e.sd[j]) - (s + s);
            Wk[r * 128 + j] = __expf(-d * inv2h);
        }
        __syncthreads();

        // rowsums: warps 0..7 reduce rows 0..7
        if (wid < 8) {
            float v = Wk[wid*128 + lane] + Wk[wid*128 + lane + 32]
                    + Wk[wid*128 + lane + 64] + Wk[wid*128 + lane + 96];
            #pragma unroll
            for (int off = 16; off > 0; off >>= 1)
                v += __shfl_down_sync(0xFFFFFFFFu, v, off);
            if (lane == 0) sm.e.rs[wid] = v;
        }
        __syncthreads();

        // kern @ Q : j split into quarters across 4 thread groups
        {
            int c = t & 127, h4 = t >> 7;
            float acc8[8];
            #pragma unroll
            for (int r = 0; r < 8; r++) acc8[r] = 0.f;
            int jb0 = h4 * 8;
            #pragma unroll 4
            for (int j4 = jb0; j4 < jb0 + 8; j4++) {
                int j = 4 * j4;
                float q0 = g_Q[(j    ) * NP + c];
                float q1 = g_Q[(j + 1) * NP + c];
                float q2 = g_Q[(j + 2) * NP + c];
                float q3 = g_Q[(j + 3) * NP + c];
                #pragma unroll
                for (int r = 0; r < 8; r++) {
                    float4 w4 = sm.e.Wk4[r][j4];
                    acc8[r] += w4.x*q0 + w4.y*q1 + w4.z*q2 + w4.w*q3;
                }
            }
            #pragma unroll
            for (int r = 0; r < 8; r++) sm.e.pacc[h4][r][c] = acc8[r];
        }
        __syncthreads();

        // combine into Wb
        #pragma unroll
        for (int p = 0; p < 2; p++) {
            int idx = t + p * 512;
            int r = idx >> 7, c = idx & 127;
            int i = r0 + r;
            float a = sm.e.pacc[0][r][c] + sm.e.pacc[1][r][c]
                    + sm.e.pacc[2][r][c] + sm.e.pacc[3][r][c];
            Wb[r * 128 + c] = Wk[r * 128 + c]
                            + invh128 * (a - sm.e.rs[r] * g_Q[i * NP + c]);
        }
        __syncthreads();

        // out: rows r0..r0+7 x cols cg*256..+255 ; each thread 4 rows
        {
            int c2 = cg * 256 + (t & 255);
            int rb = (t >> 8) * 4;
            float acc[4];
            #pragma unroll
            for (int r = 0; r < 4; r++) acc[r] = 0.f;
            #pragma unroll 4
            for (int j4 = 0; j4 < 32; j4++) {
                int j = 4 * j4;
                float g0 = G[(j    ) * DD + c2];
                float g1 = G[(j + 1) * DD + c2];
                float g2 = G[(j + 2) * DD + c2];
                float g3 = G[(j + 3) * DD + c2];
                #pragma unroll
                for (int r = 0; r < 4; r++) {
                    float4 w4 = sm.e.Wb4[rb + r][j4];
                    acc[r] += w4.x*g0 + w4.y*g1 + w4.z*g2 + w4.w*g3;
                }
            }
            #pragma unroll
            for (int r = 0; r < 4; r++) out[(r0 + rb + r) * DD + c2] = acc[r];
        }
    }
}

extern "C" void kernel_launch(void* const* d_in, const int* in_sizes, int n_in,
                              void* d_out, int out_size)
{
    const float* var  = (const float*)d_in[0];
    const float* grad = (const float*)d_in[1];
    float* out = (float*)d_out;
    stein_fused<<<NBLK, NTHR>>>(var, grad, out);
}

// round 12
// speedup vs baseline: 1.9864x; 1.1160x over previous
#include <cuda_runtime.h>
#include <math.h>

#define NP   128
#define DD   2048
#define NN   16384
#define NBLK 148
#define NTHR 512
#define ZSL  32      // K slices in phase A

// ---------------- scratch (no allocations allowed) ----------------
__device__ float    g_part[ZSL*NN];   // phase-A partials
__device__ float    g_dump[NBLK*NTHR];
__device__ float    g_Q[NN];          // Q = V G^T
__device__ float    g_S4[4*NN];       // S = Q Q^T / 128 in four K-quarters (sum them)
__device__ unsigned g_cnt[16*32];     // 16 leaf counters, 128B apart
__device__ unsigned g_root[32];
__device__ unsigned g_epoch[32];      // monotonic barrier epoch

// ---------------- shared memory union ----------------
struct SmemAll {
    union {
        struct { float4 As4[64][17]; float4 Bs4[64][17]; } a;            // 34.8 KB GEMM
        struct { float4 pc[256][4]; } r;                                  // combine (aliases a)
        struct { float pacc[4][128]; } bred;                              // phase B combine
        struct { float sd[128];
                 unsigned hist[256]; unsigned wsum[8]; unsigned sel[4]; } m;  // median
        struct { float sd[128]; float rs[8];
                 float4 Wk4[8][32];
                 float pacc[8192];                                        // 32 KB partials
                 float4 Wb4[8][32]; } e;                                  // ~40.5 KB EF
    };
};

// ---------------- acquire/release helpers ----------------
__device__ __forceinline__ unsigned ld_acq(unsigned* p) {
    unsigned v;
    asm volatile("ld.acquire.gpu.u32 %0, [%1];" : "=r"(v) : "l"(p) : "memory");
    return v;
}
__device__ __forceinline__ void st_rel(unsigned* p, unsigned v) {
    asm volatile("st.release.gpu.u32 [%0], %1;" :: "l"(p), "r"(v) : "memory");
}

// ---------------- grid barrier: 16-leaf tree, monotonic epoch ----------------
// 148 blocks: leaves 0..3 get 10 blocks, leaves 4..15 get 9.
__device__ __forceinline__ void gbar(unsigned v, int b) {
    __syncthreads();
    if (threadIdx.x == 0) {
        __threadfence();
        int leaf = b & 15;
        unsigned leafsz = (leaf < 4) ? 10u : 9u;
        unsigned r = atomicAdd(&g_cnt[leaf * 32], 1u);
        if (r == leafsz * v - 1u) {
            unsigned r2 = atomicAdd(&g_root[0], 1u);
            if (r2 == 16u * v - 1u) st_rel(&g_epoch[0], v);
        }
        while (ld_acq(&g_epoch[0]) < v) __nanosleep(16);
        __threadfence();
    }
    __syncthreads();
}

// ============================================================
// 64x64 tile of A x B^T over one 64-wide K chunk, 512 threads.
// ============================================================
__device__ __forceinline__ void dot64w(SmemAll* sm,
                                       const float* __restrict__ A,
                                       const float* __restrict__ B,
                                       float* __restrict__ C,
                                       int arow0, int brow0, int k0,
                                       int K, float scale)
{
    int t = threadIdx.x;
    int tx = t & 15, ty = (t >> 4) & 15, kh = t >> 8;
    const float4* A4 = (const float4*)A;
    const float4* B4 = (const float4*)B;
    int K4 = K >> 2, q0 = k0 >> 2;
    float* Asf = (float*)&sm->a.As4[0][0];   // row stride 68 floats
    float* Bsf = (float*)&sm->a.Bs4[0][0];

    float acc[4][4];
    #pragma unroll
    for (int i = 0; i < 4; i++)
        #pragma unroll
        for (int j = 0; j < 4; j++) acc[i][j] = 0.f;

    #pragma unroll
    for (int p = 0; p < 4; p++) {
        int idx = t + p * 512;                  // 0..2047
        int mat = idx >> 10;                    // 0=A, 1=B
        int rr = (idx >> 4) & 63, q = idx & 15;
        const float4* S4 = mat ? B4 : A4;
        float* D = mat ? Bsf : Asf;
        int row0 = mat ? brow0 : arow0;
        float4 v = S4[(row0 + rr) * K4 + q0 + q];
        int cp = (((rr >> 2) ^ q) << 2) | (rr & 3);
        int kb = 4 * q;
        D[(kb    ) * 68 + cp] = v.x;
        D[(kb + 1) * 68 + cp] = v.y;
        D[(kb + 2) * 68 + cp] = v.z;
        D[(kb + 3) * 68 + cp] = v.w;
    }
    __syncthreads();
    int kb0 = kh * 32;
    #pragma unroll 8
    for (int k = kb0; k < kb0 + 32; k++) {
        int s = k >> 2;
        float4 av = sm->a.As4[k][ty ^ s];
        float4 bv = sm->a.Bs4[k][tx ^ s];
        acc[0][0] += av.x*bv.x; acc[0][1] += av.x*bv.y; acc[0][2] += av.x*bv.z; acc[0][3] += av.x*bv.w;
        acc[1][0] += av.y*bv.x; acc[1][1] += av.y*bv.y; acc[1][2] += av.y*bv.z; acc[1][3] += av.y*bv.w;
        acc[2][0] += av.z*bv.x; acc[2][1] += av.z*bv.y; acc[2][2] += av.z*bv.z; acc[2][3] += av.z*bv.w;
        acc[3][0] += av.w*bv.x; acc[3][1] += av.w*bv.y; acc[3][2] += av.w*bv.z; acc[3][3] += av.w*bv.w;
    }
    __syncthreads();                            // done reading As/Bs (pc aliases)
    int slot = ty * 16 + tx;
    if (kh == 1) {
        #pragma unroll
        for (int i = 0; i < 4; i++)
            sm->r.pc[slot][i] = make_float4(acc[i][0], acc[i][1], acc[i][2], acc[i][3]);
    }
    __syncthreads();
    if (kh == 0) {
        #pragma unroll
        for (int i = 0; i < 4; i++) {
            float4 o = sm->r.pc[slot][i];
            o.x = (o.x + acc[i][0]) * scale;
            o.y = (o.y + acc[i][1]) * scale;
            o.z = (o.z + acc[i][2]) * scale;
            o.w = (o.w + acc[i][3]) * scale;
            *(float4*)&C[(arow0 + 4*ty + i) * NP + brow0 + 4*tx] = o;
        }
    }
}

// ============================================================
// 64x64 tile of A x B^T over one 32-wide K chunk (phase C quarters).
// ============================================================
__device__ __forceinline__ void dot64q(SmemAll* sm,
                                       const float* __restrict__ A,
                                       const float* __restrict__ B,
                                       float* __restrict__ C,
                                       int arow0, int brow0, int k0,
                                       int K, float scale)
{
    int t = threadIdx.x;
    int tx = t & 15, ty = (t >> 4) & 15, kh = t >> 8;
    const float4* A4 = (const float4*)A;
    const float4* B4 = (const float4*)B;
    int K4 = K >> 2, q0 = k0 >> 2;
    float* Asf = (float*)&sm->a.As4[0][0];
    float* Bsf = (float*)&sm->a.Bs4[0][0];

    float acc[4][4];
    #pragma unroll
    for (int i = 0; i < 4; i++)
        #pragma unroll
        for (int j = 0; j < 4; j++) acc[i][j] = 0.f;

    #pragma unroll
    for (int p = 0; p < 2; p++) {
        int idx = t + p * 512;                  // 0..1023
        int mat = idx >> 9;                     // 0=A, 1=B
        int rr = (idx >> 3) & 63, q = idx & 7;
        const float4* S4 = mat ? B4 : A4;
        float* D = mat ? Bsf : Asf;
        int row0 = mat ? brow0 : arow0;
        float4 v = S4[(row0 + rr) * K4 + q0 + q];
        int cp = (((rr >> 2) ^ q) << 2) | (rr & 3);
        int kb = 4 * q;
        D[(kb    ) * 68 + cp] = v.x;
        D[(kb + 1) * 68 + cp] = v.y;
        D[(kb + 2) * 68 + cp] = v.z;
        D[(kb + 3) * 68 + cp] = v.w;
    }
    __syncthreads();
    int kb0 = kh * 16;
    #pragma unroll 8
    for (int k = kb0; k < kb0 + 16; k++) {
        int s = k >> 2;
        float4 av = sm->a.As4[k][ty ^ s];
        float4 bv = sm->a.Bs4[k][tx ^ s];
        acc[0][0] += av.x*bv.x; acc[0][1] += av.x*bv.y; acc[0][2] += av.x*bv.z; acc[0][3] += av.x*bv.w;
        acc[1][0] += av.y*bv.x; acc[1][1] += av.y*bv.y; acc[1][2] += av.y*bv.z; acc[1][3] += av.y*bv.w;
        acc[2][0] += av.z*bv.x; acc[2][1] += av.z*bv.y; acc[2][2] += av.z*bv.z; acc[2][3] += av.z*bv.w;
        acc[3][0] += av.w*bv.x; acc[3][1] += av.w*bv.y; acc[3][2] += av.w*bv.z; acc[3][3] += av.w*bv.w;
    }
    __syncthreads();
    int slot = ty * 16 + tx;
    if (kh == 1) {
        #pragma unroll
        for (int i = 0; i < 4; i++)
            sm->r.pc[slot][i] = make_float4(acc[i][0], acc[i][1], acc[i][2], acc[i][3]);
    }
    __syncthreads();
    if (kh == 0) {
        #pragma unroll
        for (int i = 0; i < 4; i++) {
            float4 o = sm->r.pc[slot][i];
            o.x = (o.x + acc[i][0]) * scale;
            o.y = (o.y + acc[i][1]) * scale;
            o.z = (o.z + acc[i][2]) * scale;
            o.w = (o.w + acc[i][3]) * scale;
            *(float4*)&C[(arow0 + 4*ty + i) * NP + brow0 + 4*tx] = o;
        }
    }
}

__device__ __forceinline__ unsigned f2key(float d) {
    unsigned u = __float_as_uint(d);
    return (u & 0x80000000u) ? ~u : (u | 0x80000000u);
}

#define KSENT 0xFFFFFFFFu
#define ZKEY  0x80000000u   // f2key(0.0f)

// ==================================================================
__global__ void __launch_bounds__(NTHR, 1)
stein_fused(const float* __restrict__ V, const float* __restrict__ G,
            float* __restrict__ out)
{
    __shared__ SmemAll sm;
    int b = blockIdx.x, t = threadIdx.x;
    int lane = t & 31, wid = t >> 5;
    unsigned base = ld_acq(&g_epoch[0]);   // settled epoch from previous launch

    // ---- Phase A: Q partials, 4 tiles x 32 K-slices of 64 (blocks 0..127) ----
    if (b < 128) {
        int tile = b & 3, z = b >> 2;
        dot64w(&sm, V, G, g_part + z * NN, (tile >> 1) * 64, (tile & 1) * 64,
               z * 64, DD, 1.0f);
    }
    gbar(base + 1, b);

    // ---- Phase B: reduce 32 partials -> Q (blocks 0..127, 128 elems each) ----
    if (b < 128) {
        int e0 = b * 128 + (t & 127);
        int qy = t >> 7;                       // quarter 0..3
        float s = 0.f;
        #pragma unroll
        for (int z = 0; z < 8; z++) s += g_part[(qy * 8 + z) * NN + e0];
        sm.bred.pacc[qy][t & 127] = s;
        __syncthreads();
        if (t < 128)
            g_Q[b * 128 + t] = sm.bred.pacc[0][t] + sm.bred.pacc[1][t]
                             + sm.bred.pacc[2][t] + sm.bred.pacc[3][t];
    }
    gbar(base + 2, b);

    // ---- Phase C: S quarters = Q Q^T / 128 (blocks 0..15); others prewarm L1 ----
    if (b < 16) {
        int khq = b & 3, tile = b >> 2;
        dot64q(&sm, g_Q, g_Q, g_S4 + khq * NN, (tile >> 1) * 64, (tile & 1) * 64,
               khq * 32, NP, 1.0f / 128.0f);
    } else if (b < 128) {
        // warm L1 with this block's EF working set (G column slice + Q)
        float acc = 0.f;
        if (t < 256) {
            int c2 = (b & 7) * 256 + t;
            #pragma unroll 8
            for (int j = 0; j < 128; j++) acc += G[j * DD + c2];
        } else {
            int c = t & 127;
            #pragma unroll 8
            for (int j = 0; j < 128; j++) acc += g_Q[j * NP + c];
        }
        g_dump[b * NTHR + t] = acc;            // keep loads alive (dead data)
    }
    gbar(base + 3, b);

    if (b >= 128) return;   // barrier-only blocks exit

    // ========== Phase M (replicated; symmetric; 2-pass radix, mid-bucket) ==========
    if (t < 128)
        sm.m.sd[t] = g_S4[t * NP + t] + g_S4[NN + t * NP + t]
                   + g_S4[2*NN + t * NP + t] + g_S4[3*NN + t * NP + t];
    __syncthreads();

    unsigned keys[32];
    {
        int i = t >> 2, j0q = (t & 3) * 32;
        float sdi = sm.m.sd[i];
        const float4* S0 = (const float4*)(g_S4 + 0*NN + i * NP + j0q);
        const float4* S1 = (const float4*)(g_S4 + 1*NN + i * NP + j0q);
        const float4* S2 = (const float4*)(g_S4 + 2*NN + i * NP + j0q);
        const float4* S3 = (const float4*)(g_S4 + 3*NN + i * NP + j0q);
        #pragma unroll
        for (int e4 = 0; e4 < 8; e4++) {
            int j = j0q + 4 * e4;
            if (j + 3 > i) {
                float4 a0 = S0[e4], a1 = S1[e4], a2 = S2[e4], a3 = S3[e4];
                float s0 = a0.x + a1.x + a2.x + a3.x;
                float s1 = a0.y + a1.y + a2.y + a3.y;
                float s2 = a0.z + a1.z + a2.z + a3.z;
                float s3 = a0.w + a1.w + a2.w + a3.w;
                keys[4*e4+0] = (j+0 > i) ? f2key((sdi + sm.m.sd[j+0]) - (s0 + s0)) : KSENT;
                keys[4*e4+1] = (j+1 > i) ? f2key((sdi + sm.m.sd[j+1]) - (s1 + s1)) : KSENT;
                keys[4*e4+2] = (j+2 > i) ? f2key((sdi + sm.m.sd[j+2]) - (s2 + s2)) : KSENT;
                keys[4*e4+3] = (j+3 > i) ? f2key((sdi + sm.m.sd[j+3]) - (s3 + s3)) : KSENT;
            } else {
                keys[4*e4+0] = KSENT; keys[4*e4+1] = KSENT;
                keys[4*e4+2] = KSENT; keys[4*e4+3] = KSENT;
            }
        }
    }

    unsigned hi_mask = 0u, hi_val = 0u, krank = 8192u;
    #pragma unroll
    for (int p = 0; p < 2; p++) {
        int shift = 24 - 8 * p;
        if (t < 256) sm.m.hist[t] = 0u;
        __syncthreads();
        if (p == 0) {
            // all keys active: warp-aggregate, weight 2 each; sentinels land in bin 255
            #pragma unroll
            for (int e = 0; e < 32; e++) {
                unsigned bin = keys[e] >> 24;
                unsigned mm = __match_any_sync(0xFFFFFFFFu, bin);
                if ((int)(__ffs(mm) - 1) == lane)
                    atomicAdd(&sm.m.hist[bin], 2u * (unsigned)__popc(mm));
            }
            if (t == 0) atomicAdd(&sm.m.hist[ZKEY >> 24], 128u);   // diag zeros
        } else {
            #pragma unroll
            for (int e = 0; e < 32; e++) {
                unsigned key = keys[e];
                if ((key & hi_mask) == hi_val)
                    atomicAdd(&sm.m.hist[(key >> shift) & 255u], 2u);
            }
            if (t == 0 && (ZKEY & hi_mask) == hi_val)
                atomicAdd(&sm.m.hist[(ZKEY >> shift) & 255u], 128u);
        }
        __syncthreads();
        unsigned v = 0, incl = 0;
        if (t < 256) {
            v = sm.m.hist[t]; incl = v;
            #pragma unroll
            for (int off = 1; off < 32; off <<= 1) {
                unsigned nv = __shfl_up_sync(0xFFFFFFFFu, incl, off);
                if (lane >= off) incl += nv;
            }
            if (lane == 31) sm.m.wsum[wid] = incl;
        }
        __syncthreads();
        if (t < 8) {
            unsigned w = sm.m.wsum[t], in2 = w;
            #pragma unroll
            for (int off = 1; off < 8; off <<= 1) {
                unsigned nv = __shfl_up_sync(0xFFu, in2, off);
                if (t >= off) in2 += nv;
            }
            sm.m.wsum[t] = in2 - w;
        }
        __syncthreads();
        if (t < 256) {
            unsigned excl = incl - v + sm.m.wsum[wid];
            if (excl <= krank && krank < excl + v) {
                sm.m.sel[0] = (unsigned)t;
                sm.m.sel[1] = krank - excl;
            }
        }
        __syncthreads();
        hi_mask |= (0xFFu << shift);
        hi_val  |= (sm.m.sel[0] << shift);
        krank    = sm.m.sel[1];
        __syncthreads();
    }
    // mid-bucket key: h is ~1e4x larger than dMsd, so 0.2% med error is harmless
    unsigned medkey = hi_val | 0x8000u;

    float inv2h, invh128;
    {
        unsigned u = (medkey & 0x80000000u) ? (medkey ^ 0x80000000u) : ~medkey;
        float med = __uint_as_float(u);
        float h = (med * med) / 6.9314718f;   // ln(128)
        inv2h = 0.5f / h;
        invh128 = 1.0f / (h * 128.0f);
    }
    __syncthreads();    // m -> e union switch (sd at same offset, preserved)

    // ================= Phase EF =================
    {
        int r0 = (b >> 3) * 8, cg = b & 7;
        float* Wk = (float*)&sm.e.Wk4[0][0];
        float* Wb = (float*)&sm.e.Wb4[0][0];

        // kern rows r0..r0+7 (2 per thread)
        #pragma unroll
        for (int p = 0; p < 2; p++) {
            int idx = t + p * 512;
            int r = idx >> 7, j = idx & 127;
            int i = r0 + r;
            float s = g_S4[i * NP + j] + g_S4[NN + i * NP + j]
                    + g_S4[2*NN + i * NP + j] + g_S4[3*NN + i * NP + j];
            float d = (sm.e.sd[i] + sm.e.sd[j]) - (s + s);
            Wk[r * 128 + j] = __expf(-d * inv2h);
        }
        __syncthreads();

        // rowsums: warps 0..7 reduce rows 0..7
        if (wid < 8) {
            float v = Wk[wid*128 + lane] + Wk[wid*128 + lane + 32]
                    + Wk[wid*128 + lane + 64] + Wk[wid*128 + lane + 96];
            #pragma unroll
            for (int off = 16; off > 0; off >>= 1)
                v += __shfl_down_sync(0xFFFFFFFFu, v, off);
            if (lane == 0) sm.e.rs[wid] = v;
        }
        __syncthreads();

        // kern @ Q : vectorized. thread = (colpair 0..63, jchunk 0..7 of 16)
        {
            int cpair = t & 63, chunk = t >> 6;
            const float2* Q2 = (const float2*)g_Q;    // row stride 64 float2
            float2 acc[8];
            #pragma unroll
            for (int r = 0; r < 8; r++) acc[r] = make_float2(0.f, 0.f);
            #pragma unroll
            for (int jb = 0; jb < 4; jb++) {
                int j = chunk * 16 + jb * 4;
                float4 wv[8];
                #pragma unroll
                for (int r = 0; r < 8; r++) wv[r] = sm.e.Wk4[r][j >> 2];
                #pragma unroll
                for (int dj = 0; dj < 4; dj++) {
                    float2 q2 = Q2[(j + dj) * 64 + cpair];
                    #pragma unroll
                    for (int r = 0; r < 8; r++) {
                        float w = (dj == 0) ? wv[r].x : (dj == 1) ? wv[r].y
                                : (dj == 2) ? wv[r].z : wv[r].w;
                        acc[r].x += w * q2.x;
                        acc[r].y += w * q2.y;
                    }
                }
            }
            float2* pQ = (float2*)sm.e.pacc;          // [8 chunks][8 r][64 cpair]
            #pragma unroll
            for (int r = 0; r < 8; r++) pQ[(chunk * 8 + r) * 64 + cpair] = acc[r];
        }
        __syncthreads();

        // combine into Wb (2 entries per thread)
        #pragma unroll
        for (int p = 0; p < 2; p++) {
            int idx = t + p * 512;
            int r = idx >> 7, c = idx & 127;
            int i = r0 + r;
            float a = 0.f;
            #pragma unroll
            for (int ch = 0; ch < 8; ch++) a += sm.e.pacc[(ch * 8 + r) * 128 + c];
            Wb[r * 128 + c] = Wk[r * 128 + c]
                            + invh128 * (a - sm.e.rs[r] * g_Q[i * NP + c]);
        }
        __syncthreads();

        // out GEMM: vectorized. thread = (colpair 0..127, jchunk 0..3 of 32)
        {
            int cpair = t & 127, chunk = t >> 7;
            const float2* G2 = (const float2*)G;      // row stride 1024 float2
            int gcol = cg * 128 + cpair;
            float2 acc[8];
            #pragma unroll
            for (int r = 0; r < 8; r++) acc[r] = make_float2(0.f, 0.f);
            #pragma unroll
            for (int jb = 0; jb < 8; jb++) {
                int j = chunk * 32 + jb * 4;
                float4 wv[8];
                #pragma unroll
                for (int r = 0; r < 8; r++) wv[r] = sm.e.Wb4[r][j >> 2];
                #pragma unroll
                for (int dj = 0; dj < 4; dj++) {
                    float2 g2 = G2[(j + dj) * 1024 + gcol];
                    #pragma unroll
                    for (int r = 0; r < 8; r++) {
                        float w = (dj == 0) ? wv[r].x : (dj == 1) ? wv[r].y
                                : (dj == 2) ? wv[r].z : wv[r].w;
                        acc[r].x += w * g2.x;
                        acc[r].y += w * g2.y;
                    }
                }
            }
            float2* pO = (float2*)sm.e.pacc;          // [4 chunks][8 r][128 cpair]
            #pragma unroll
            for (int r = 0; r < 8; r++) pO[(chunk * 8 + r) * 128 + cpair] = acc[r];
        }
        __syncthreads();

        // combine + store: 4 outputs per thread
        #pragma unroll
        for (int p = 0; p < 4; p++) {
            int idx = t + p * 512;
            int r = idx >> 8, c = idx & 255;
            float v = sm.e.pacc[ r       * 256 + c] + sm.e.pacc[( 8 + r) * 256 + c]
                    + sm.e.pacc[(16 + r) * 256 + c] + sm.e.pacc[(24 + r) * 256 + c];
            out[(r0 + r) * DD + cg * 256 + c] = v;
        }
    }
}

extern "C" void kernel_launch(void* const* d_in, const int* in_sizes, int n_in,
                              void* d_out, int out_size)
{
    const float* var  = (const float*)d_in[0];
    const float* grad = (const float*)d_in[1];
    float* out = (float*)d_out;
    stein_fused<<<NBLK, NTHR>>>(var, grad, out);
}